// round 2
// baseline (speedup 1.0000x reference)
#include <cuda_runtime.h>
#include <math.h>

#define EMBD 256
#define HID  512
#define BATCH 64
#define SEQ  512
#define NG   2048      // 4*HID
#define WROW 768       // EMB+HID
#define NCLS 50257
#define NCTA_LSTM 128

// ---------------- scratch (static device globals; no cudaMalloc allowed) ----
__device__ float g_Gx[(size_t)SEQ * BATCH * NG];   // 268 MB: precomputed x-projection + bias
__device__ float g_h[2][HID * BATCH];              // hidden state, transposed [j][b]
__device__ float g_hbt[BATCH * HID];               // final hidden, [b][j]
__device__ unsigned g_bar_count;                   // zero-init, returns to 0 each launch
__device__ volatile unsigned g_bar_gen;            // monotonically increasing across replays

// ---------------- grid-wide software barrier (all CTAs resident) -----------
__device__ __forceinline__ void grid_barrier(unsigned nctas) {
    __threadfence();          // make this thread's global writes visible
    __syncthreads();
    if (threadIdx.x == 0) {
        unsigned g = g_bar_gen;
        if (atomicAdd(&g_bar_count, 1) == nctas - 1) {
            g_bar_count = 0;
            __threadfence();
            g_bar_gen = g + 1;
        } else {
            while (g_bar_gen == g) { __nanosleep(32); }
        }
        __threadfence();
    }
    __syncthreads();
}

// ============================================================================
// Kernel 1: Gx[m][g] = sum_k emb[tok(m)][k] * Wx[g][k] + bias[g]
//   m = t*64 + b  (M=32768), g in [0,2048), k in [0,256)
//   Tiled GEMM: BM=64, BN=64, BK=32, 256 threads, 4x4 per thread.
// ============================================================================
#define BM 64
#define BN 64
#define BK 32

__global__ __launch_bounds__(256) void gx_kernel(
    const int* __restrict__ x, const float* __restrict__ emb,
    const float* __restrict__ W, const float* __restrict__ bias)
{
    __shared__ float As[BM][BK + 1];
    __shared__ float Bs[BN][BK + 1];
    __shared__ int   tok[BM];

    const int tid = threadIdx.x;
    const int m0 = blockIdx.x * BM;
    const int n0 = blockIdx.y * BN;

    if (tid < BM) {
        int m = m0 + tid;
        int b = m & 63, t = m >> 6;
        tok[tid] = x[b * SEQ + t];
    }
    __syncthreads();

    const int tx = tid & 15, ty = tid >> 4;
    float acc[4][4];
#pragma unroll
    for (int i = 0; i < 4; i++)
#pragma unroll
        for (int j = 0; j < 4; j++) acc[i][j] = 0.f;

    for (int k0 = 0; k0 < EMBD; k0 += BK) {
#pragma unroll
        for (int i = 0; i < 8; i++) {           // A: 64x32 = 2048 elems
            int e = tid + i * 256;
            int r = e >> 5, c = e & 31;
            As[r][c] = emb[(size_t)tok[r] * EMBD + k0 + c];
        }
#pragma unroll
        for (int i = 0; i < 8; i++) {           // B (Wx): Bs[n][k]
            int e = tid + i * 256;
            int r = e >> 5, c = e & 31;
            Bs[r][c] = W[(size_t)(n0 + r) * WROW + k0 + c];
        }
        __syncthreads();
#pragma unroll
        for (int k = 0; k < BK; k++) {
            float a[4], bb[4];
#pragma unroll
            for (int i = 0; i < 4; i++) a[i]  = As[ty * 4 + i][k];
#pragma unroll
            for (int i = 0; i < 4; i++) bb[i] = Bs[tx * 4 + i][k];
#pragma unroll
            for (int i = 0; i < 4; i++)
#pragma unroll
                for (int j = 0; j < 4; j++)
                    acc[i][j] = fmaf(a[i], bb[j], acc[i][j]);
        }
        __syncthreads();
    }

#pragma unroll
    for (int i = 0; i < 4; i++) {
        int m = m0 + ty * 4 + i;
#pragma unroll
        for (int j = 0; j < 4; j++) {
            int g = n0 + tx * 4 + j;
            g_Gx[(size_t)m * NG + g] = acc[i][j] + bias[g];
        }
    }
}

// ============================================================================
// Kernel 2: persistent LSTM recurrence, 512 steps, grid barrier per step.
//   128 CTAs x 256 threads. CTA owns 4 hidden units j; thread owns (b, j).
//   smem: hs[k][b] (128KB, restaged per step) + ws (4j x 4gates x 512, 32KB,
//   loaded once).
// ============================================================================
__global__ __launch_bounds__(256, 1) void lstm_kernel(const float* __restrict__ W)
{
    extern __shared__ float smem[];
    float*  hs  = smem;                         // HID*BATCH floats
    float*  wsf = smem + HID * BATCH;           // 4*4*HID floats

    const int tid = threadIdx.x;
    const int b   = tid & 63;
    const int jl  = tid >> 6;                   // 0..3
    const int j   = blockIdx.x * 4 + jl;

    // load this CTA's 16 Wh rows once (resident for the whole kernel)
    for (int i = tid; i < 4 * 4 * HID; i += 256) {
        int jj  = i / (4 * HID);
        int rem = i % (4 * HID);
        int g   = rem / HID;
        int k   = rem % HID;
        wsf[(jj * 4 + g) * HID + k] =
            W[(size_t)(g * HID + blockIdx.x * 4 + jj) * WROW + EMBD + k];
    }
    // zero both h buffers
    for (int i = blockIdx.x * 256 + tid; i < 2 * HID * BATCH; i += NCTA_LSTM * 256)
        ((float*)g_h)[i] = 0.f;

    float C = 0.f, h = 0.f;
    grid_barrier(NCTA_LSTM);

    const float4* w0 = (const float4*)(wsf + (jl * 4 + 0) * HID);
    const float4* w1 = (const float4*)(wsf + (jl * 4 + 1) * HID);
    const float4* w2 = (const float4*)(wsf + (jl * 4 + 2) * HID);
    const float4* w3 = (const float4*)(wsf + (jl * 4 + 3) * HID);

    int cur = 0;
    for (int t = 0; t < SEQ; t++) {
        // restage h (transposed layout [j][b] -> hs[k*64+b]) from global
        {
            const float4* src = (const float4*)g_h[cur];
            float4* dst = (float4*)hs;
#pragma unroll 8
            for (int i = tid; i < HID * BATCH / 4; i += 256) dst[i] = src[i];
        }
        __syncthreads();

        const float* gx = &g_Gx[((size_t)t * BATCH + b) * NG];
        float af = gx[j];
        float ai = gx[j + HID];
        float ao = gx[j + 2 * HID];
        float ac = gx[j + 3 * HID];

#pragma unroll 8
        for (int k4 = 0; k4 < HID / 4; k4++) {
            float4 vf = w0[k4];
            float4 vi = w1[k4];
            float4 vo = w2[k4];
            float4 vc = w3[k4];
            const float* hp = hs + (k4 * 4) * BATCH + b;
            float h0 = hp[0], h1 = hp[BATCH], h2 = hp[2 * BATCH], h3 = hp[3 * BATCH];
            af = fmaf(h0, vf.x, af); ai = fmaf(h0, vi.x, ai);
            ao = fmaf(h0, vo.x, ao); ac = fmaf(h0, vc.x, ac);
            af = fmaf(h1, vf.y, af); ai = fmaf(h1, vi.y, ai);
            ao = fmaf(h1, vo.y, ao); ac = fmaf(h1, vc.y, ac);
            af = fmaf(h2, vf.z, af); ai = fmaf(h2, vi.z, ai);
            ao = fmaf(h2, vo.z, ao); ac = fmaf(h2, vc.z, ac);
            af = fmaf(h3, vf.w, af); ai = fmaf(h3, vi.w, ai);
            ao = fmaf(h3, vo.w, ao); ac = fmaf(h3, vc.w, ac);
        }

        float fg = 1.f / (1.f + expf(-af));
        float ig = 1.f / (1.f + expf(-ai));
        float og = 1.f / (1.f + expf(-ao));
        float ct = tanhf(ac);
        C = fg * C + ig * ct;
        h = og * tanhf(C);

        g_h[cur ^ 1][j * BATCH + b] = h;
        grid_barrier(NCTA_LSTM);   // writes visible + hs safe to overwrite
        cur ^= 1;
    }

    g_hbt[b * HID + j] = h;        // final h, [b][j] layout for classifier
}

// ============================================================================
// Kernel 3: out[b][n] = h[b] . fc_weight[n] + fc_bias[n]
//   One warp per class n; lanes split k; 64 batch accumulators per thread.
// ============================================================================
__global__ __launch_bounds__(256, 1) void fc_kernel(
    const float* __restrict__ fcw, const float* __restrict__ fcb,
    float* __restrict__ out)
{
    extern __shared__ float hb[];  // [b][k], 32768 floats
    const int tid = threadIdx.x;
    for (int i = tid; i < BATCH * HID / 4; i += 256)
        ((float4*)hb)[i] = ((const float4*)g_hbt)[i];
    __syncthreads();

    const int warp = tid >> 5, lane = tid & 31;
    const int wglobal = blockIdx.x * 8 + warp;
    const int nw = gridDim.x * 8;

    for (int n = wglobal; n < NCLS; n += nw) {
        float acc[64];
#pragma unroll
        for (int i = 0; i < 64; i++) acc[i] = 0.f;
        const float* wrow = fcw + (size_t)n * HID;
#pragma unroll
        for (int kk = 0; kk < HID; kk += 32) {
            float wv = wrow[kk + lane];
#pragma unroll
            for (int bb = 0; bb < 64; bb++)
                acc[bb] = fmaf(wv, hb[bb * HID + kk + lane], acc[bb]);
        }
        float bias = fcb[n];
#pragma unroll
        for (int bb = 0; bb < 64; bb++) {
            float v = acc[bb];
            v += __shfl_xor_sync(0xffffffffu, v, 16);
            v += __shfl_xor_sync(0xffffffffu, v, 8);
            v += __shfl_xor_sync(0xffffffffu, v, 4);
            v += __shfl_xor_sync(0xffffffffu, v, 2);
            v += __shfl_xor_sync(0xffffffffu, v, 1);
            if (lane == 0) out[(size_t)bb * NCLS + n] = v + bias;
        }
    }
}

// ============================================================================
extern "C" void kernel_launch(void* const* d_in, const int* in_sizes, int n_in,
                              void* d_out, int out_size)
{
    const int*   x   = (const int*)d_in[0];
    const float* emb = (const float*)d_in[1];
    const float* W   = (const float*)d_in[2];
    const float* Wb  = (const float*)d_in[3];
    const float* fcw = (const float*)d_in[4];
    const float* fcb = (const float*)d_in[5];
    float* out = (float*)d_out;

    static const size_t lstm_smem = (size_t)(HID * BATCH + 4 * 4 * HID) * 4; // 163840
    static const size_t fc_smem   = (size_t)BATCH * HID * 4;                 // 131072
    cudaFuncSetAttribute(lstm_kernel, cudaFuncAttributeMaxDynamicSharedMemorySize,
                         (int)lstm_smem);
    cudaFuncSetAttribute(fc_kernel, cudaFuncAttributeMaxDynamicSharedMemorySize,
                         (int)fc_smem);

    // 1) input projection for all timesteps (parallel GEMM, bias folded in)
    dim3 g1(SEQ * BATCH / BM, NG / BN);
    gx_kernel<<<g1, 256>>>(x, emb, W, Wb);

    // 2) persistent recurrence, grid barrier per step
    lstm_kernel<<<NCTA_LSTM, 256, lstm_smem>>>(W);

    // 3) classifier
    fc_kernel<<<148, 256, fc_smem>>>(fcw, fcb, out);
}

// round 3
// speedup vs baseline: 1.0515x; 1.0515x over previous
#include <cuda_runtime.h>
#include <math.h>

#define EMBD 256
#define HID  512
#define BATCH 64
#define SEQ  512
#define NG   2048      // 4*HID
#define WROW 768       // EMB+HID
#define NCLS 50257
#define NCTA 128

// ---------------- scratch (static device globals; no cudaMalloc allowed) ----
__device__ float g_Gx[(size_t)SEQ * BATCH * NG];   // [t][b][g] x-projection + bias
// h in pair-interleaved layout: float2 element at [(j>>1)*64 + p*2 + (j&1)]
// holds (h[b=2p][j], h[b=2p+1][j]).
__device__ float g_h[2][HID * BATCH];
__device__ float g_hbt[BATCH * HID];               // final hidden, [b][j]
__device__ unsigned g_bar_count;
__device__ volatile unsigned g_bar_gen;

// ---------------- grid-wide software barrier (all CTAs resident) -----------
__device__ __forceinline__ void grid_barrier(unsigned nctas) {
    __threadfence();
    __syncthreads();
    if (threadIdx.x == 0) {
        unsigned g = g_bar_gen;
        if (atomicAdd(&g_bar_count, 1) == nctas - 1) {
            g_bar_count = 0;
            __threadfence();
            g_bar_gen = g + 1;
        } else {
            while (g_bar_gen == g) { __nanosleep(32); }
        }
        __threadfence();
    }
    __syncthreads();
}

// ---------------- packed f32x2 FMA (B300: same issue rate as scalar FFMA) --
__device__ __forceinline__ void fma2(unsigned long long& d,
                                     unsigned long long a,
                                     unsigned long long b) {
    asm("fma.rn.f32x2 %0, %1, %2, %0;" : "+l"(d) : "l"(a), "l"(b));
}
union U2 { float2 f; unsigned long long u; };
union U4 { float4 f; ulonglong2 u; };

// ============================================================================
// Kernel 1: Gx[t][b][g] = emb[x[b,t]] . Wx[g] + bias[g]
//   GEMM M=32768 (m=t*64+b), N=2048, K=256. 128x128 tile, BK=16, 8x8/thread.
// ============================================================================
__global__ __launch_bounds__(256) void gx_kernel(
    const int* __restrict__ x, const float* __restrict__ emb,
    const float* __restrict__ W, const float* __restrict__ bias)
{
    __shared__ float As[16][128];
    __shared__ float Bs[16][128];
    __shared__ int   tok[128];

    const int tid = threadIdx.x;
    const int m0 = blockIdx.x * 128;
    const int n0 = blockIdx.y * 128;

    if (tid < 128) {
        int m = m0 + tid;
        tok[tid] = x[(m & 63) * SEQ + (m >> 6)];
    }
    __syncthreads();

    const int lm = tid & 127, lq = tid >> 7;   // loader: row, quad-half
    const int tx = tid & 15,  ty = tid >> 4;   // compute: col grp, row grp

    float acc[8][8];
#pragma unroll
    for (int i = 0; i < 8; i++)
#pragma unroll
        for (int jj = 0; jj < 8; jj++) acc[i][jj] = 0.f;

    float4 ra0, ra1, rb0, rb1;
    {
        const float* arow = emb + (size_t)tok[lm] * EMBD;
        ra0 = *(const float4*)(arow + lq * 4);
        ra1 = *(const float4*)(arow + 8 + lq * 4);
        const float* brow = W + (size_t)(n0 + lm) * WROW;
        rb0 = *(const float4*)(brow + lq * 4);
        rb1 = *(const float4*)(brow + 8 + lq * 4);
    }

    for (int kt = 0; kt < 16; kt++) {
        As[lq * 4 + 0][lm] = ra0.x; As[lq * 4 + 1][lm] = ra0.y;
        As[lq * 4 + 2][lm] = ra0.z; As[lq * 4 + 3][lm] = ra0.w;
        As[8 + lq * 4 + 0][lm] = ra1.x; As[8 + lq * 4 + 1][lm] = ra1.y;
        As[8 + lq * 4 + 2][lm] = ra1.z; As[8 + lq * 4 + 3][lm] = ra1.w;
        Bs[lq * 4 + 0][lm] = rb0.x; Bs[lq * 4 + 1][lm] = rb0.y;
        Bs[lq * 4 + 2][lm] = rb0.z; Bs[lq * 4 + 3][lm] = rb0.w;
        Bs[8 + lq * 4 + 0][lm] = rb1.x; Bs[8 + lq * 4 + 1][lm] = rb1.y;
        Bs[8 + lq * 4 + 2][lm] = rb1.z; Bs[8 + lq * 4 + 3][lm] = rb1.w;
        __syncthreads();

        if (kt < 15) {                         // prefetch next k-tile
            int k0 = (kt + 1) * 16;
            const float* arow = emb + (size_t)tok[lm] * EMBD + k0;
            ra0 = *(const float4*)(arow + lq * 4);
            ra1 = *(const float4*)(arow + 8 + lq * 4);
            const float* brow = W + (size_t)(n0 + lm) * WROW + k0;
            rb0 = *(const float4*)(brow + lq * 4);
            rb1 = *(const float4*)(brow + 8 + lq * 4);
        }

#pragma unroll
        for (int k = 0; k < 16; k++) {
            float4 aL = *(const float4*)&As[k][ty * 4];
            float4 aH = *(const float4*)&As[k][64 + ty * 4];
            float4 bL = *(const float4*)&Bs[k][tx * 4];
            float4 bH = *(const float4*)&Bs[k][64 + tx * 4];
            float av[8] = {aL.x, aL.y, aL.z, aL.w, aH.x, aH.y, aH.z, aH.w};
            float bv[8] = {bL.x, bL.y, bL.z, bL.w, bH.x, bH.y, bH.z, bH.w};
#pragma unroll
            for (int i = 0; i < 8; i++)
#pragma unroll
                for (int jj = 0; jj < 8; jj++)
                    acc[i][jj] = fmaf(av[i], bv[jj], acc[i][jj]);
        }
        __syncthreads();
    }

    float4 biL = *(const float4*)(bias + n0 + tx * 4);
    float4 biH = *(const float4*)(bias + n0 + 64 + tx * 4);
#pragma unroll
    for (int br = 0; br < 2; br++)
#pragma unroll
        for (int i = 0; i < 4; i++) {
            int m = m0 + br * 64 + ty * 4 + i;
            float* orow = g_Gx + (size_t)m * NG + n0;
            int r = br * 4 + i;
            float4 v0 = make_float4(acc[r][0] + biL.x, acc[r][1] + biL.y,
                                    acc[r][2] + biL.z, acc[r][3] + biL.w);
            float4 v1 = make_float4(acc[r][4] + biH.x, acc[r][5] + biH.y,
                                    acc[r][6] + biH.z, acc[r][7] + biH.w);
            *(float4*)(orow + tx * 4) = v0;
            *(float4*)(orow + 64 + tx * 4) = v1;
        }
}

// ============================================================================
// Kernel 2: persistent LSTM recurrence, f32x2 packed FMA.
//   128 CTAs x 256 threads. thread = (pair p -> b=2p,2p+1 ; jl 0..3 ; kh 0..1)
//   CTA owns j in [4*bx, 4*bx+4). Each thread does half the K range; the two
//   halves reduce through smem.
// ============================================================================
__global__ __launch_bounds__(256, 1) void lstm_kernel(const float* __restrict__ W)
{
    extern __shared__ float smem[];
    float2* hs2 = (float2*)smem;                       // 16384 float2 (128KB)
    float2* ws2 = (float2*)(smem + 2 * 16384);         // 8192 float2 (64KB) dup'd
    float2* red = (float2*)(smem + 2 * 16384 + 2 * 8192); // 512 float2 (4KB)

    const int tid = threadIdx.x;
    const int p  = tid & 31;
    const int jl = (tid >> 5) & 3;
    const int kh = tid >> 7;
    const int j  = blockIdx.x * 4 + jl;

    // duplicated Wh rows for this CTA: ws2[(jl*4+g)*HID + k] = {w, w}
    for (int i = tid; i < 16 * HID; i += 256) {
        int jj  = i / (4 * HID);
        int rem = i % (4 * HID);
        int g   = rem / HID;
        int k   = rem % HID;
        float w = W[(size_t)(g * HID + blockIdx.x * 4 + jj) * WROW + EMBD + k];
        ws2[(jj * 4 + g) * HID + k] = make_float2(w, w);
    }
    for (int i = blockIdx.x * 256 + tid; i < 2 * HID * BATCH; i += NCTA * 256)
        ((float*)g_h)[i] = 0.f;

    float2 C = make_float2(0.f, 0.f);
    float2 hlast = make_float2(0.f, 0.f);
    grid_barrier(NCTA);

    const float4* w0 = (const float4*)(ws2 + (jl * 4 + 0) * HID + kh * 256);
    const float4* w1 = (const float4*)(ws2 + (jl * 4 + 1) * HID + kh * 256);
    const float4* w2 = (const float4*)(ws2 + (jl * 4 + 2) * HID + kh * 256);
    const float4* w3 = (const float4*)(ws2 + (jl * 4 + 3) * HID + kh * 256);

    int cur = 0;
    for (int t = 0; t < SEQ; t++) {
        // restage h (straight copy; layout already pair+k-pair interleaved)
        {
            const float4* src = (const float4*)g_h[cur];
            float4* dst = (float4*)hs2;
#pragma unroll 8
            for (int i = tid; i < HID * BATCH / 4; i += 256) dst[i] = src[i];
        }

        unsigned long long accf, acci, acco, accc;
        if (kh == 0) {
            const float* gx0 = g_Gx + ((size_t)t * BATCH + 2 * p) * NG + j;
            const float* gx1 = gx0 + NG;
            U2 v;
            v.f = make_float2(gx0[0],        gx1[0]);        accf = v.u;
            v.f = make_float2(gx0[HID],      gx1[HID]);      acci = v.u;
            v.f = make_float2(gx0[2 * HID],  gx1[2 * HID]);  acco = v.u;
            v.f = make_float2(gx0[3 * HID],  gx1[3 * HID]);  accc = v.u;
        } else {
            accf = acci = acco = accc = 0ull;   // bit pattern of (0.f, 0.f)
        }
        __syncthreads();

        const float4* hs4 = (const float4*)hs2;
#pragma unroll 8
        for (int it = 0; it < 128; it++) {
            U4 hh; hh.f = hs4[(kh * 128 + it) * 32 + p];   // h pair for k, k+1
            U4 wf, wi, wo, wc;
            wf.f = w0[it]; wi.f = w1[it]; wo.f = w2[it]; wc.f = w3[it];
            fma2(accf, hh.u.x, wf.u.x);
            fma2(acci, hh.u.x, wi.u.x);
            fma2(acco, hh.u.x, wo.u.x);
            fma2(accc, hh.u.x, wc.u.x);
            fma2(accf, hh.u.y, wf.u.y);
            fma2(acci, hh.u.y, wi.u.y);
            fma2(acco, hh.u.y, wo.u.y);
            fma2(accc, hh.u.y, wc.u.y);
        }

        if (kh) {
            float2* r = red + (tid - 128) * 4;
            U2 v;
            v.u = accf; r[0] = v.f;
            v.u = acci; r[1] = v.f;
            v.u = acco; r[2] = v.f;
            v.u = accc; r[3] = v.f;
        }
        __syncthreads();
        if (!kh) {
            const float2* r = red + tid * 4;
            U2 f, ig, o, c;
            f.u = accf; ig.u = acci; o.u = acco; c.u = accc;
            f.f.x  += r[0].x; f.f.y  += r[0].y;
            ig.f.x += r[1].x; ig.f.y += r[1].y;
            o.f.x  += r[2].x; o.f.y  += r[2].y;
            c.f.x  += r[3].x; c.f.y  += r[3].y;

            float Fx = 1.f / (1.f + expf(-f.f.x));
            float Fy = 1.f / (1.f + expf(-f.f.y));
            float Ix = 1.f / (1.f + expf(-ig.f.x));
            float Iy = 1.f / (1.f + expf(-ig.f.y));
            float Ox = 1.f / (1.f + expf(-o.f.x));
            float Oy = 1.f / (1.f + expf(-o.f.y));
            float Tx = tanhf(c.f.x);
            float Ty = tanhf(c.f.y);
            C.x = Fx * C.x + Ix * Tx;
            C.y = Fy * C.y + Iy * Ty;
            hlast.x = Ox * tanhf(C.x);
            hlast.y = Oy * tanhf(C.y);
            // pair + k-pair interleaved layout (straight-copy restage)
            ((float2*)g_h[cur ^ 1])[(j >> 1) * 64 + p * 2 + (j & 1)] = hlast;
        }
        grid_barrier(NCTA);
        cur ^= 1;
    }

    if (!kh) {
        g_hbt[(size_t)(2 * p) * HID + j]     = hlast.x;
        g_hbt[(size_t)(2 * p + 1) * HID + j] = hlast.y;
    }
}

// ============================================================================
// Kernel 3: out[b][n] = h[b] . fc_weight[n] + fc_bias[n]
// ============================================================================
__global__ __launch_bounds__(256, 1) void fc_kernel(
    const float* __restrict__ fcw, const float* __restrict__ fcb,
    float* __restrict__ out)
{
    extern __shared__ float hb[];  // [b][k]
    const int tid = threadIdx.x;
    for (int i = tid; i < BATCH * HID / 4; i += 256)
        ((float4*)hb)[i] = ((const float4*)g_hbt)[i];
    __syncthreads();

    const int warp = tid >> 5, lane = tid & 31;
    const int wglobal = blockIdx.x * 8 + warp;
    const int nw = gridDim.x * 8;

    for (int n = wglobal; n < NCLS; n += nw) {
        float acc[64];
#pragma unroll
        for (int i = 0; i < 64; i++) acc[i] = 0.f;
        const float* wrow = fcw + (size_t)n * HID;
#pragma unroll
        for (int kk = 0; kk < HID; kk += 32) {
            float wv = wrow[kk + lane];
#pragma unroll
            for (int bb = 0; bb < 64; bb++)
                acc[bb] = fmaf(wv, hb[bb * HID + kk + lane], acc[bb]);
        }
        float bias = fcb[n];
#pragma unroll
        for (int bb = 0; bb < 64; bb++) {
            float v = acc[bb];
            v += __shfl_xor_sync(0xffffffffu, v, 16);
            v += __shfl_xor_sync(0xffffffffu, v, 8);
            v += __shfl_xor_sync(0xffffffffu, v, 4);
            v += __shfl_xor_sync(0xffffffffu, v, 2);
            v += __shfl_xor_sync(0xffffffffu, v, 1);
            if (lane == 0) out[(size_t)bb * NCLS + n] = v + bias;
        }
    }
}

// ============================================================================
extern "C" void kernel_launch(void* const* d_in, const int* in_sizes, int n_in,
                              void* d_out, int out_size)
{
    const int*   x   = (const int*)d_in[0];
    const float* emb = (const float*)d_in[1];
    const float* W   = (const float*)d_in[2];
    const float* Wb  = (const float*)d_in[3];
    const float* fcw = (const float*)d_in[4];
    const float* fcb = (const float*)d_in[5];
    float* out = (float*)d_out;

    static const size_t lstm_smem = (size_t)(2 * 16384 + 2 * 8192 + 2 * 512) * 4; // 200704B
    static const size_t fc_smem   = (size_t)BATCH * HID * 4;                      // 131072B
    cudaFuncSetAttribute(lstm_kernel, cudaFuncAttributeMaxDynamicSharedMemorySize,
                         (int)lstm_smem);
    cudaFuncSetAttribute(fc_kernel, cudaFuncAttributeMaxDynamicSharedMemorySize,
                         (int)fc_smem);

    dim3 g1(SEQ * BATCH / 128, NG / 128);
    gx_kernel<<<g1, 256>>>(x, emb, W, Wb);

    lstm_kernel<<<NCTA, 256, lstm_smem>>>(W);

    fc_kernel<<<148, 256, fc_smem>>>(fcw, fcb, out);
}

// round 4
// speedup vs baseline: 1.2187x; 1.1590x over previous
#include <cuda_runtime.h>
#include <math.h>

#define EMBD 256
#define HID  512
#define BATCH 64
#define SEQ  512
#define NG   2048      // 4*HID
#define WROW 768       // EMB+HID
#define NCLS 50257
#define NCTA 128
#define HS_STRIDE 516  // padded floats per h row in smem (129 float4, odd quads)

// ---------------- scratch (static device globals; no cudaMalloc allowed) ----
__device__ float g_Gx[(size_t)SEQ * NG * BATCH];   // [t][g][b]  (transposed!)
__device__ float g_h[2][BATCH * HID];              // [b][k]
__device__ float g_hbt[BATCH * HID];               // final hidden, [b][j]
__device__ volatile unsigned g_arrive[NCTA];
__device__ volatile unsigned g_release;
__device__ unsigned g_epoch;                       // bumped each launch (replay-safe)

// ---------------- flag-tree grid barrier (all 128 CTAs resident) ------------
__device__ __forceinline__ void gbar(int bx, int tid, unsigned gen) {
    __threadfence();
    __syncthreads();
    if (bx == 0) {
        if (tid > 0 && tid < NCTA) {
            while (g_arrive[tid] < gen) { }
        }
        __syncthreads();
        if (tid == 0) { __threadfence(); g_release = gen; }
    } else {
        if (tid == 0) {
            g_arrive[bx] = gen;
            while (g_release < gen) { }
        }
    }
    __syncthreads();
}

// ---------------- packed f32x2 FMA ------------------------------------------
__device__ __forceinline__ void fma2(unsigned long long& d,
                                     unsigned long long a,
                                     unsigned long long b) {
    asm("fma.rn.f32x2 %0, %1, %2, %0;" : "+l"(d) : "l"(a), "l"(b));
}
union U2 { float2 f; unsigned long long u; };
union U4 { float4 f; ulonglong2 u; };
__device__ __forceinline__ float usum(unsigned long long v) {
    U2 x; x.u = v; return x.f.x + x.f.y;
}

// ============================================================================
// Kernel 1: Gx = emb[x] . WxT + bias, output TRANSPOSED as [t][g][b].
//   GEMM M=32768 (m=t*64+b), N=2048, K=256. 128x128 tile, BK=16, 8x8/thread.
//   Epilogue stages 16-column slices through smem to write [g][b]-coalesced.
// ============================================================================
__global__ __launch_bounds__(256) void gx_kernel(
    const int* __restrict__ x, const float* __restrict__ emb,
    const float* __restrict__ W, const float* __restrict__ bias)
{
    __shared__ float As[16][128];
    __shared__ float Bs[16][128];
    __shared__ int   tok[128];

    const int tid = threadIdx.x;
    const int m0 = blockIdx.x * 128;
    const int n0 = blockIdx.y * 128;

    if (tid < 128) {
        int m = m0 + tid;
        tok[tid] = x[(m & 63) * SEQ + (m >> 6)];
    }
    __syncthreads();

    const int lm = tid & 127, lq = tid >> 7;
    const int tx = tid & 15,  ty = tid >> 4;

    float acc[8][8];
#pragma unroll
    for (int i = 0; i < 8; i++)
#pragma unroll
        for (int jj = 0; jj < 8; jj++) acc[i][jj] = 0.f;

    float4 ra0, ra1, rb0, rb1;
    {
        const float* arow = emb + (size_t)tok[lm] * EMBD;
        ra0 = *(const float4*)(arow + lq * 4);
        ra1 = *(const float4*)(arow + 8 + lq * 4);
        const float* brow = W + (size_t)(n0 + lm) * WROW;
        rb0 = *(const float4*)(brow + lq * 4);
        rb1 = *(const float4*)(brow + 8 + lq * 4);
    }

    for (int kt = 0; kt < 16; kt++) {
        As[lq * 4 + 0][lm] = ra0.x; As[lq * 4 + 1][lm] = ra0.y;
        As[lq * 4 + 2][lm] = ra0.z; As[lq * 4 + 3][lm] = ra0.w;
        As[8 + lq * 4 + 0][lm] = ra1.x; As[8 + lq * 4 + 1][lm] = ra1.y;
        As[8 + lq * 4 + 2][lm] = ra1.z; As[8 + lq * 4 + 3][lm] = ra1.w;
        Bs[lq * 4 + 0][lm] = rb0.x; Bs[lq * 4 + 1][lm] = rb0.y;
        Bs[lq * 4 + 2][lm] = rb0.z; Bs[lq * 4 + 3][lm] = rb0.w;
        Bs[8 + lq * 4 + 0][lm] = rb1.x; Bs[8 + lq * 4 + 1][lm] = rb1.y;
        Bs[8 + lq * 4 + 2][lm] = rb1.z; Bs[8 + lq * 4 + 3][lm] = rb1.w;
        __syncthreads();

        if (kt < 15) {
            int k0 = (kt + 1) * 16;
            const float* arow = emb + (size_t)tok[lm] * EMBD + k0;
            ra0 = *(const float4*)(arow + lq * 4);
            ra1 = *(const float4*)(arow + 8 + lq * 4);
            const float* brow = W + (size_t)(n0 + lm) * WROW + k0;
            rb0 = *(const float4*)(brow + lq * 4);
            rb1 = *(const float4*)(brow + 8 + lq * 4);
        }

#pragma unroll
        for (int k = 0; k < 16; k++) {
            float4 aL = *(const float4*)&As[k][ty * 4];
            float4 aH = *(const float4*)&As[k][64 + ty * 4];
            float4 bL = *(const float4*)&Bs[k][tx * 4];
            float4 bH = *(const float4*)&Bs[k][64 + tx * 4];
            float av[8] = {aL.x, aL.y, aL.z, aL.w, aH.x, aH.y, aH.z, aH.w};
            float bv[8] = {bL.x, bL.y, bL.z, bL.w, bH.x, bH.y, bH.z, bH.w};
#pragma unroll
            for (int i = 0; i < 8; i++)
#pragma unroll
                for (int jj = 0; jj < 8; jj++)
                    acc[i][jj] = fmaf(av[i], bv[jj], acc[i][jj]);
        }
        __syncthreads();
    }

    // fold in bias
    {
        float4 biL = *(const float4*)(bias + n0 + tx * 4);
        float4 biH = *(const float4*)(bias + n0 + 64 + tx * 4);
        float bl[8] = {biL.x, biL.y, biL.z, biL.w, biH.x, biH.y, biH.z, biH.w};
#pragma unroll
        for (int r = 0; r < 8; r++)
#pragma unroll
            for (int cc = 0; cc < 8; cc++) acc[r][cc] += bl[cc];
    }

    // transposed store: 8 stages of 16 columns through As (16x128 floats)
    float* T = &As[0][0];
    for (int s = 0; s < 8; s++) {
        __syncthreads();
        int txg = s & 3;
        int jbase = (s < 4) ? 0 : 4;
        if ((tx >> 2) == txg) {
#pragma unroll
            for (int q = 0; q < 4; q++) {
                int cl = (tx & 3) * 4 + q;
#pragma unroll
                for (int r = 0; r < 8; r++) {
                    int m_loc = (r >> 2) * 64 + ty * 4 + (r & 3);
                    T[cl * 128 + m_loc] = acc[r][jbase + q];
                }
            }
        }
        __syncthreads();
#pragma unroll
        for (int w = 0; w < 2; w++) {
            int v = tid + w * 256;             // float4 index 0..511
            int row = v >> 4;                  // (cl, t_loc)
            int within = v & 15;               // b/4
            int cl = row >> 1, tl = row & 1;
            float4 val = *(float4*)&T[cl * 128 + tl * 64 + within * 4];
            int t = (m0 >> 6) + tl;
            int gcol = n0 + s * 16 + cl;
            *(float4*)&g_Gx[((size_t)t * NG + gcol) * BATCH + within * 4] = val;
        }
    }
}

// ============================================================================
// Kernel 2: persistent LSTM recurrence.
//   128 CTAs x 128 threads (warp = jl, lane = p). Thread: j = 4*bx+jl,
//   batches {p, p+32}, all 4 gates, full k=512. k-paired f32x2 accumulators.
//   Weights in smem (non-dup, warp-broadcast loads). h restaged in 4 chunks
//   overlapped with compute.
// ============================================================================
__global__ __launch_bounds__(128, 1) void lstm_kernel(const float* __restrict__ W)
{
    extern __shared__ float smem[];
    float* hs = smem;                        // 64 x 516 (padded)
    float* ws = smem + BATCH * HS_STRIDE;    // 16 x 512

    const int tid = threadIdx.x;
    const int bx  = blockIdx.x;
    const int p   = tid & 31;
    const int jl  = tid >> 5;
    const int j   = bx * 4 + jl;
    const unsigned base = g_epoch;           // read before any flag writes

    // load this CTA's 16 Wh rows once: ws[(jlw*4+g)*512 + k]
    for (int i = tid; i < 16 * HID; i += 128) {
        int row = i >> 9;                    // 0..15
        int k   = i & 511;
        int jlw = row >> 2, g = row & 3;
        ws[i] = W[(size_t)(g * HID + bx * 4 + jlw) * WROW + EMBD + k];
    }
    // zero h buffer 0
    for (int i = bx * 128 + tid; i < BATCH * HID; i += NCTA * 128)
        g_h[0][i] = 0.f;

    gbar(bx, tid, base + 1);

    const float4* wf4 = (const float4*)(ws + (jl * 4 + 0) * HID);
    const float4* wi4 = (const float4*)(ws + (jl * 4 + 1) * HID);
    const float4* wo4 = (const float4*)(ws + (jl * 4 + 2) * HID);
    const float4* wc4 = (const float4*)(ws + (jl * 4 + 3) * HID);
    const float4* h0p = (const float4*)(hs + p * HS_STRIDE);
    const float4* h1p = (const float4*)(hs + (p + 32) * HS_STRIDE);

    float C0 = 0.f, C1 = 0.f, hv0 = 0.f, hv1 = 0.f;
    int cur = 0;

    for (int t = 0; t < SEQ; t++) {
        const float4* src = (const float4*)g_h[cur];   // [b][512] rows of 128 f4
        float4* dst = (float4*)hs;                     // rows of 129 f4

        // restage chunk 0 (k in [0,128))
#pragma unroll
        for (int i = 0; i < 16; i++) {
            int e = tid + (i << 7);
            int b = e >> 5, c4 = e & 31;
            dst[b * 129 + c4] = __ldcg(src + b * 128 + c4);
        }

        // gate-bias (gx) loads: coalesced [t][g][b]
        const float* gxt = g_Gx + (size_t)t * NG * BATCH;
        float gf0 = __ldcg(gxt + (size_t)(0 * HID + j) * BATCH + p);
        float gf1 = __ldcg(gxt + (size_t)(0 * HID + j) * BATCH + p + 32);
        float gi0 = __ldcg(gxt + (size_t)(1 * HID + j) * BATCH + p);
        float gi1 = __ldcg(gxt + (size_t)(1 * HID + j) * BATCH + p + 32);
        float go0 = __ldcg(gxt + (size_t)(2 * HID + j) * BATCH + p);
        float go1 = __ldcg(gxt + (size_t)(2 * HID + j) * BATCH + p + 32);
        float gc0 = __ldcg(gxt + (size_t)(3 * HID + j) * BATCH + p);
        float gc1 = __ldcg(gxt + (size_t)(3 * HID + j) * BATCH + p + 32);
        __syncthreads();

        unsigned long long f0 = 0, f1 = 0, i0 = 0, i1 = 0,
                           o0 = 0, o1 = 0, c0 = 0, c1 = 0;

        for (int c = 0; c < 4; c++) {
            float4 rr[16];
            if (c < 3) {                      // prefetch next chunk
                int off = (c + 1) * 32;
#pragma unroll
                for (int i = 0; i < 16; i++) {
                    int e = tid + (i << 7);
                    int b = e >> 5, c4 = e & 31;
                    rr[i] = __ldcg(src + b * 128 + off + c4);
                }
            }
            int kq0 = c * 32;
#pragma unroll 8
            for (int kq = kq0; kq < kq0 + 32; kq++) {
                U4 wf, wi, wo, wc, ha, hb;
                wf.f = wf4[kq]; wi.f = wi4[kq];
                wo.f = wo4[kq]; wc.f = wc4[kq];
                ha.f = h0p[kq]; hb.f = h1p[kq];
                fma2(f0, ha.u.x, wf.u.x); fma2(f0, ha.u.y, wf.u.y);
                fma2(i0, ha.u.x, wi.u.x); fma2(i0, ha.u.y, wi.u.y);
                fma2(o0, ha.u.x, wo.u.x); fma2(o0, ha.u.y, wo.u.y);
                fma2(c0, ha.u.x, wc.u.x); fma2(c0, ha.u.y, wc.u.y);
                fma2(f1, hb.u.x, wf.u.x); fma2(f1, hb.u.y, wf.u.y);
                fma2(i1, hb.u.x, wi.u.x); fma2(i1, hb.u.y, wi.u.y);
                fma2(o1, hb.u.x, wo.u.x); fma2(o1, hb.u.y, wo.u.y);
                fma2(c1, hb.u.x, wc.u.x); fma2(c1, hb.u.y, wc.u.y);
            }
            if (c < 3) {
                int off = (c + 1) * 32;
#pragma unroll
                for (int i = 0; i < 16; i++) {
                    int e = tid + (i << 7);
                    int b = e >> 5, c4 = e & 31;
                    dst[b * 129 + off + c4] = rr[i];
                }
                __syncthreads();
            }
        }

        // epilogue: nonlinearity + state update for both batches
        {
            float af = usum(f0) + gf0, ai = usum(i0) + gi0;
            float ao = usum(o0) + go0, ac = usum(c0) + gc0;
            float F = 1.f / (1.f + expf(-af));
            float I = 1.f / (1.f + expf(-ai));
            float O = 1.f / (1.f + expf(-ao));
            C0 = F * C0 + I * tanhf(ac);
            hv0 = O * tanhf(C0);
        }
        {
            float af = usum(f1) + gf1, ai = usum(i1) + gi1;
            float ao = usum(o1) + go1, ac = usum(c1) + gc1;
            float F = 1.f / (1.f + expf(-af));
            float I = 1.f / (1.f + expf(-ai));
            float O = 1.f / (1.f + expf(-ao));
            C1 = F * C1 + I * tanhf(ac);
            hv1 = O * tanhf(C1);
        }
        g_h[cur ^ 1][p * HID + j]        = hv0;
        g_h[cur ^ 1][(p + 32) * HID + j] = hv1;

        gbar(bx, tid, base + 2 + t);
        cur ^= 1;
    }

    g_hbt[(size_t)p * HID + j]        = hv0;
    g_hbt[(size_t)(p + 32) * HID + j] = hv1;

    if (bx == 0 && tid == 0) g_epoch = base + SEQ + 8;   // for next replay
}

// ============================================================================
// Kernel 3: out[b][n] = h[b] . fc_weight[n] + fc_bias[n]
// ============================================================================
__global__ __launch_bounds__(256, 1) void fc_kernel(
    const float* __restrict__ fcw, const float* __restrict__ fcb,
    float* __restrict__ out)
{
    extern __shared__ float hb[];  // [b][k]
    const int tid = threadIdx.x;
    for (int i = tid; i < BATCH * HID / 4; i += 256)
        ((float4*)hb)[i] = ((const float4*)g_hbt)[i];
    __syncthreads();

    const int warp = tid >> 5, lane = tid & 31;
    const int wglobal = blockIdx.x * 8 + warp;
    const int nw = gridDim.x * 8;

    for (int n = wglobal; n < NCLS; n += nw) {
        float acc[64];
#pragma unroll
        for (int i = 0; i < 64; i++) acc[i] = 0.f;
        const float* wrow = fcw + (size_t)n * HID;
#pragma unroll
        for (int kk = 0; kk < HID; kk += 32) {
            float wv = wrow[kk + lane];
#pragma unroll
            for (int bb = 0; bb < 64; bb++)
                acc[bb] = fmaf(wv, hb[bb * HID + kk + lane], acc[bb]);
        }
        float bias = fcb[n];
#pragma unroll
        for (int bb = 0; bb < 64; bb++) {
            float v = acc[bb];
            v += __shfl_xor_sync(0xffffffffu, v, 16);
            v += __shfl_xor_sync(0xffffffffu, v, 8);
            v += __shfl_xor_sync(0xffffffffu, v, 4);
            v += __shfl_xor_sync(0xffffffffu, v, 2);
            v += __shfl_xor_sync(0xffffffffu, v, 1);
            if (lane == 0) out[(size_t)bb * NCLS + n] = v + bias;
        }
    }
}

// ============================================================================
extern "C" void kernel_launch(void* const* d_in, const int* in_sizes, int n_in,
                              void* d_out, int out_size)
{
    const int*   x   = (const int*)d_in[0];
    const float* emb = (const float*)d_in[1];
    const float* W   = (const float*)d_in[2];
    const float* Wb  = (const float*)d_in[3];
    const float* fcw = (const float*)d_in[4];
    const float* fcb = (const float*)d_in[5];
    float* out = (float*)d_out;

    static const size_t lstm_smem = (size_t)(BATCH * HS_STRIDE + 16 * HID) * 4; // 164864
    static const size_t fc_smem   = (size_t)BATCH * HID * 4;                    // 131072
    cudaFuncSetAttribute(lstm_kernel, cudaFuncAttributeMaxDynamicSharedMemorySize,
                         (int)lstm_smem);
    cudaFuncSetAttribute(fc_kernel, cudaFuncAttributeMaxDynamicSharedMemorySize,
                         (int)fc_smem);

    dim3 g1(SEQ * BATCH / 128, NG / 128);
    gx_kernel<<<g1, 256>>>(x, emb, W, Wb);

    lstm_kernel<<<NCTA, 128, lstm_smem>>>(W);

    fc_kernel<<<148, 256, fc_smem>>>(fcw, fcb, out);
}

// round 5
// speedup vs baseline: 1.3513x; 1.1088x over previous
#include <cuda_runtime.h>
#include <math.h>

#define EMBD 256
#define HID  512
#define BATCH 64
#define SEQ  512
#define NG   2048      // 4*HID
#define WROW 768       // EMB+HID
#define NCLS 50257
#define NCTA 128
#define HS_STRIDE 516  // padded floats per h row in smem (129 float4)

// ---------------- scratch (static device globals; no cudaMalloc allowed) ----
__device__ float g_Gx[(size_t)SEQ * NG * BATCH];   // [t][g][b]  (transposed)
__device__ float g_h[2][BATCH * HID];              // [b][k]
__device__ float g_hbt[HID * BATCH];               // final hidden, [k][b]
__device__ volatile unsigned g_arrive[NCTA];
__device__ volatile unsigned g_release;
__device__ unsigned g_epoch;                       // bumped each launch (replay-safe)

// ---------------- flag-tree grid barrier (all 128 CTAs resident) ------------
__device__ __forceinline__ void gbar(int bx, int tid, unsigned gen) {
    __threadfence();
    __syncthreads();
    if (bx == 0) {
        if (tid > 0 && tid < NCTA) {
            while (g_arrive[tid] < gen) { }
        }
        __syncthreads();
        if (tid == 0) { __threadfence(); g_release = gen; }
    } else {
        if (tid == 0) {
            g_arrive[bx] = gen;
            while (g_release < gen) { }
        }
    }
    __syncthreads();
}

// ---------------- packed f32x2 helpers --------------------------------------
__device__ __forceinline__ void fma2(unsigned long long& d,
                                     unsigned long long a,
                                     unsigned long long b) {
    asm("fma.rn.f32x2 %0, %1, %2, %0;" : "+l"(d) : "l"(a), "l"(b));
}
__device__ __forceinline__ unsigned long long pack2(float v) {
    unsigned long long r;
    asm("mov.b64 %0, {%1, %1};" : "=l"(r) : "f"(v));
    return r;
}
__device__ __forceinline__ void add2(unsigned long long& d, unsigned long long a) {
    asm("add.rn.f32x2 %0, %0, %1;" : "+l"(d) : "l"(a));
}
union U2 { float2 f; unsigned long long u; };
union U4 { float4 f; ulonglong2 u; };
__device__ __forceinline__ float usum(unsigned long long v) {
    U2 x; x.u = v; return x.f.x + x.f.y;
}

// ============================================================================
// Kernel 1: Gx = emb[x] . WxT + bias, output TRANSPOSED as [t][g][b].
//   128x128 tile, BK=16, 8x8/thread, f32x2 accumulators paired along j.
// ============================================================================
__global__ __launch_bounds__(256) void gx_kernel(
    const int* __restrict__ x, const float* __restrict__ emb,
    const float* __restrict__ W, const float* __restrict__ bias)
{
    __shared__ float As[16][128];
    __shared__ float Bs[16][128];
    __shared__ int   tok[128];

    const int tid = threadIdx.x;
    const int m0 = blockIdx.x * 128;
    const int n0 = blockIdx.y * 128;

    if (tid < 128) {
        int m = m0 + tid;
        tok[tid] = x[(m & 63) * SEQ + (m >> 6)];
    }
    __syncthreads();

    const int lm = tid & 127, lq = tid >> 7;
    const int tx = tid & 15,  ty = tid >> 4;

    unsigned long long acc[8][4];
#pragma unroll
    for (int i = 0; i < 8; i++)
#pragma unroll
        for (int jp = 0; jp < 4; jp++) acc[i][jp] = 0ull;

    float4 ra0, ra1, rb0, rb1;
    {
        const float* arow = emb + (size_t)tok[lm] * EMBD;
        ra0 = *(const float4*)(arow + lq * 4);
        ra1 = *(const float4*)(arow + 8 + lq * 4);
        const float* brow = W + (size_t)(n0 + lm) * WROW;
        rb0 = *(const float4*)(brow + lq * 4);
        rb1 = *(const float4*)(brow + 8 + lq * 4);
    }

    for (int kt = 0; kt < 16; kt++) {
        As[lq * 4 + 0][lm] = ra0.x; As[lq * 4 + 1][lm] = ra0.y;
        As[lq * 4 + 2][lm] = ra0.z; As[lq * 4 + 3][lm] = ra0.w;
        As[8 + lq * 4 + 0][lm] = ra1.x; As[8 + lq * 4 + 1][lm] = ra1.y;
        As[8 + lq * 4 + 2][lm] = ra1.z; As[8 + lq * 4 + 3][lm] = ra1.w;
        Bs[lq * 4 + 0][lm] = rb0.x; Bs[lq * 4 + 1][lm] = rb0.y;
        Bs[lq * 4 + 2][lm] = rb0.z; Bs[lq * 4 + 3][lm] = rb0.w;
        Bs[8 + lq * 4 + 0][lm] = rb1.x; Bs[8 + lq * 4 + 1][lm] = rb1.y;
        Bs[8 + lq * 4 + 2][lm] = rb1.z; Bs[8 + lq * 4 + 3][lm] = rb1.w;
        __syncthreads();

        if (kt < 15) {
            int k0 = (kt + 1) * 16;
            const float* arow = emb + (size_t)tok[lm] * EMBD + k0;
            ra0 = *(const float4*)(arow + lq * 4);
            ra1 = *(const float4*)(arow + 8 + lq * 4);
            const float* brow = W + (size_t)(n0 + lm) * WROW + k0;
            rb0 = *(const float4*)(brow + lq * 4);
            rb1 = *(const float4*)(brow + 8 + lq * 4);
        }

#pragma unroll
        for (int k = 0; k < 16; k++) {
            float4 aL = *(const float4*)&As[k][ty * 4];
            float4 aH = *(const float4*)&As[k][64 + ty * 4];
            U4 bL, bH;
            bL.f = *(const float4*)&Bs[k][tx * 4];
            bH.f = *(const float4*)&Bs[k][64 + tx * 4];
            float av[8] = {aL.x, aL.y, aL.z, aL.w, aH.x, aH.y, aH.z, aH.w};
#pragma unroll
            for (int i = 0; i < 8; i++) {
                unsigned long long aa = pack2(av[i]);
                fma2(acc[i][0], aa, bL.u.x);
                fma2(acc[i][1], aa, bL.u.y);
                fma2(acc[i][2], aa, bH.u.x);
                fma2(acc[i][3], aa, bH.u.y);
            }
        }
        __syncthreads();
    }

    // unpack + bias
    float accf[8][8];
    {
        float4 biL = *(const float4*)(bias + n0 + tx * 4);
        float4 biH = *(const float4*)(bias + n0 + 64 + tx * 4);
        float bl[8] = {biL.x, biL.y, biL.z, biL.w, biH.x, biH.y, biH.z, biH.w};
#pragma unroll
        for (int i = 0; i < 8; i++)
#pragma unroll
            for (int jp = 0; jp < 4; jp++) {
                U2 u; u.u = acc[i][jp];
                accf[i][2 * jp]     = u.f.x + bl[2 * jp];
                accf[i][2 * jp + 1] = u.f.y + bl[2 * jp + 1];
            }
    }

    // transposed store: 8 stages of 16 columns through As (16x128 floats)
    float* T = &As[0][0];
    for (int s = 0; s < 8; s++) {
        __syncthreads();
        int txg = s & 3;
        int jbase = (s < 4) ? 0 : 4;
        if ((tx >> 2) == txg) {
#pragma unroll
            for (int q = 0; q < 4; q++) {
                int cl = (tx & 3) * 4 + q;
#pragma unroll
                for (int r = 0; r < 8; r++) {
                    int m_loc = (r >> 2) * 64 + ty * 4 + (r & 3);
                    T[cl * 128 + m_loc] = accf[r][jbase + q];
                }
            }
        }
        __syncthreads();
#pragma unroll
        for (int w = 0; w < 2; w++) {
            int v = tid + w * 256;
            int row = v >> 4;
            int within = v & 15;
            int cl = row >> 1, tl = row & 1;
            float4 val = *(float4*)&T[cl * 128 + tl * 64 + within * 4];
            int t = (m0 >> 6) + tl;
            int gcol = n0 + s * 16 + cl;
            *(float4*)&g_Gx[((size_t)t * NG + gcol) * BATCH + within * 4] = val;
        }
    }
}

// ============================================================================
// Kernel 2: persistent LSTM recurrence. 128 CTAs x 256 threads (8 warps,
//   2/SMSP). Thread = (b = tid&63, jl = tid>>6): one batch, j = 4*bx+jl,
//   all 4 gates, full k via k-paired f32x2. Weights smem broadcast per warp.
//   h restaged in 4 chunks overlapped with compute.
// ============================================================================
__global__ __launch_bounds__(256, 1) void lstm_kernel(const float* __restrict__ W)
{
    extern __shared__ float smem[];
    float* hs = smem;                        // 64 x 516 (padded)
    float* ws = smem + BATCH * HS_STRIDE;    // 16 x 512

    const int tid = threadIdx.x;
    const int bx  = blockIdx.x;
    const int b   = tid & 63;
    const int jl  = tid >> 6;
    const int j   = bx * 4 + jl;
    const unsigned base = g_epoch;

    for (int i = tid; i < 16 * HID; i += 256) {
        int row = i >> 9;
        int k   = i & 511;
        int jlw = row >> 2, g = row & 3;
        ws[i] = W[(size_t)(g * HID + bx * 4 + jlw) * WROW + EMBD + k];
    }
    for (int i = bx * 256 + tid; i < BATCH * HID; i += NCTA * 256)
        g_h[0][i] = 0.f;

    gbar(bx, tid, base + 1);

    const float4* wf4 = (const float4*)(ws + (jl * 4 + 0) * HID);
    const float4* wi4 = (const float4*)(ws + (jl * 4 + 1) * HID);
    const float4* wo4 = (const float4*)(ws + (jl * 4 + 2) * HID);
    const float4* wc4 = (const float4*)(ws + (jl * 4 + 3) * HID);
    const float4* hp  = (const float4*)(hs + b * HS_STRIDE);

    float C = 0.f, hv = 0.f;
    int cur = 0;

    for (int t = 0; t < SEQ; t++) {
        const float4* src = (const float4*)g_h[cur];   // [b][128 f4]
        float4* dst = (float4*)hs;                     // rows of 129 f4

        // restage chunk 0 (k in [0,128)): 2048 f4 / 256 threads
#pragma unroll
        for (int i = 0; i < 8; i++) {
            int e = tid + (i << 8);
            int bb = e >> 5, c4 = e & 31;
            dst[bb * 129 + c4] = __ldcg(src + bb * 128 + c4);
        }

        const float* gxt = g_Gx + (size_t)t * NG * BATCH;
        float gf = __ldcg(gxt + (size_t)(0 * HID + j) * BATCH + b);
        float gi = __ldcg(gxt + (size_t)(1 * HID + j) * BATCH + b);
        float go = __ldcg(gxt + (size_t)(2 * HID + j) * BATCH + b);
        float gc = __ldcg(gxt + (size_t)(3 * HID + j) * BATCH + b);
        __syncthreads();

        unsigned long long fa = 0, ia = 0, oa = 0, ca = 0;

        for (int c = 0; c < 4; c++) {
            float4 rr[8];
            if (c < 3) {
                int off = (c + 1) * 32;
#pragma unroll
                for (int i = 0; i < 8; i++) {
                    int e = tid + (i << 8);
                    int bb = e >> 5, c4 = e & 31;
                    rr[i] = __ldcg(src + bb * 128 + off + c4);
                }
            }
            int kq0 = c * 32;
#pragma unroll 8
            for (int kq = kq0; kq < kq0 + 32; kq++) {
                U4 wf, wi, wo, wc, hh;
                hh.f = hp[kq];
                wf.f = wf4[kq]; wi.f = wi4[kq];
                wo.f = wo4[kq]; wc.f = wc4[kq];
                fma2(fa, hh.u.x, wf.u.x); fma2(fa, hh.u.y, wf.u.y);
                fma2(ia, hh.u.x, wi.u.x); fma2(ia, hh.u.y, wi.u.y);
                fma2(oa, hh.u.x, wo.u.x); fma2(oa, hh.u.y, wo.u.y);
                fma2(ca, hh.u.x, wc.u.x); fma2(ca, hh.u.y, wc.u.y);
            }
            if (c < 3) {
                int off = (c + 1) * 32;
#pragma unroll
                for (int i = 0; i < 8; i++) {
                    int e = tid + (i << 8);
                    int bb = e >> 5, c4 = e & 31;
                    dst[bb * 129 + off + c4] = rr[i];
                }
                __syncthreads();
            }
        }

        float af = usum(fa) + gf, ai = usum(ia) + gi;
        float ao = usum(oa) + go, ac = usum(ca) + gc;
        float F = 1.f / (1.f + expf(-af));
        float I = 1.f / (1.f + expf(-ai));
        float O = 1.f / (1.f + expf(-ao));
        C = F * C + I * tanhf(ac);
        hv = O * tanhf(C);

        g_h[cur ^ 1][b * HID + j] = hv;

        gbar(bx, tid, base + 2 + t);
        cur ^= 1;
    }

    g_hbt[(size_t)j * BATCH + b] = hv;            // [k][b] for fc
    if (bx == 0 && tid == 0) g_epoch = base + SEQ + 8;
}

// ============================================================================
// Kernel 3: out[b][n] = h[b] . fc_weight[n] + fc_bias[n]
//   h staged in smem as [k][b] padded to 68 floats/row. Lane = k-slice,
//   f32x2 accumulators paired over batch, u64 shuffle reduction.
// ============================================================================
__global__ __launch_bounds__(256, 1) void fc_kernel(
    const float* __restrict__ fcw, const float* __restrict__ fcb,
    float* __restrict__ out)
{
    extern __shared__ float hb2[];   // 512 rows x 68 floats
    const int tid = threadIdx.x;
    for (int i = tid; i < HID * 16; i += 256) {   // 8192 f4
        int k = i >> 4, q = i & 15;
        ((float4*)(hb2 + k * 68))[q] = ((const float4*)g_hbt)[i];
    }
    __syncthreads();

    const int warp = tid >> 5, lane = tid & 31;
    const int wglobal = blockIdx.x * 8 + warp;
    const int nw = gridDim.x * 8;

    for (int n = wglobal; n < NCLS; n += nw) {
        unsigned long long acc[32];
#pragma unroll
        for (int i = 0; i < 32; i++) acc[i] = 0ull;
        const float* wrow = fcw + (size_t)n * HID;
#pragma unroll
        for (int kk = 0; kk < 16; kk++) {
            int k = kk * 32 + lane;
            unsigned long long ww = pack2(wrow[k]);
            const float4* hrow = (const float4*)(hb2 + k * 68);
#pragma unroll
            for (int q = 0; q < 16; q++) {
                U4 hh; hh.f = hrow[q];
                fma2(acc[2 * q],     ww, hh.u.x);
                fma2(acc[2 * q + 1], ww, hh.u.y);
            }
        }
        float bias = fcb[n];
#pragma unroll
        for (int p = 0; p < 32; p++) {
            unsigned long long v = acc[p];
            add2(v, __shfl_xor_sync(0xffffffffu, v, 16));
            add2(v, __shfl_xor_sync(0xffffffffu, v, 8));
            add2(v, __shfl_xor_sync(0xffffffffu, v, 4));
            add2(v, __shfl_xor_sync(0xffffffffu, v, 2));
            add2(v, __shfl_xor_sync(0xffffffffu, v, 1));
            if (lane == 0) {
                U2 u; u.u = v;
                out[(size_t)(2 * p) * NCLS + n]     = u.f.x + bias;
                out[(size_t)(2 * p + 1) * NCLS + n] = u.f.y + bias;
            }
        }
    }
}

// ============================================================================
extern "C" void kernel_launch(void* const* d_in, const int* in_sizes, int n_in,
                              void* d_out, int out_size)
{
    const int*   x   = (const int*)d_in[0];
    const float* emb = (const float*)d_in[1];
    const float* W   = (const float*)d_in[2];
    const float* Wb  = (const float*)d_in[3];
    const float* fcw = (const float*)d_in[4];
    const float* fcb = (const float*)d_in[5];
    float* out = (float*)d_out;

    static const size_t lstm_smem = (size_t)(BATCH * HS_STRIDE + 16 * HID) * 4; // 164864
    static const size_t fc_smem   = (size_t)HID * 68 * 4;                       // 139264
    cudaFuncSetAttribute(lstm_kernel, cudaFuncAttributeMaxDynamicSharedMemorySize,
                         (int)lstm_smem);
    cudaFuncSetAttribute(fc_kernel, cudaFuncAttributeMaxDynamicSharedMemorySize,
                         (int)fc_smem);

    dim3 g1(SEQ * BATCH / 128, NG / 128);
    gx_kernel<<<g1, 256>>>(x, emb, W, Wb);

    lstm_kernel<<<NCTA, 256, lstm_smem>>>(W);

    fc_kernel<<<148, 256, fc_smem>>>(fcw, fcb, out);
}

// round 7
// speedup vs baseline: 1.4413x; 1.0666x over previous
#include <cuda_runtime.h>
#include <math.h>

#define EMBD 256
#define HID  512
#define BATCH 64
#define SEQ  512
#define NG   2048      // 4*HID
#define WROW 768       // EMB+HID
#define NCLS 50257
#define NCTA 128
#define HS_STRIDE 516  // padded floats per h row in smem (129 float4)

// ---------------- scratch (static device globals; no cudaMalloc allowed) ----
__device__ float g_Gx[(size_t)SEQ * NG * BATCH];   // [t][g][b]  (transposed)
__device__ float g_h[2][BATCH * HID];              // [b][k]
__device__ float g_hbt[HID * BATCH];               // final hidden, [k][b]
__device__ volatile unsigned g_arrive[NCTA];
__device__ volatile unsigned g_release;
__device__ unsigned g_epoch;                       // bumped each launch (replay-safe)

// ---------------- flag-tree grid barrier (all 128 CTAs resident) ------------
__device__ __forceinline__ void gbar(int bx, int tid, unsigned gen) {
    __threadfence();
    __syncthreads();
    if (bx == 0) {
        if (tid > 0 && tid < NCTA) {
            while (g_arrive[tid] < gen) { }
        }
        __syncthreads();
        if (tid == 0) { __threadfence(); g_release = gen; }
    } else {
        if (tid == 0) {
            g_arrive[bx] = gen;
            while (g_release < gen) { }
        }
    }
    __syncthreads();
}

// ---------------- packed f32x2 helpers --------------------------------------
__device__ __forceinline__ void fma2(unsigned long long& d,
                                     unsigned long long a,
                                     unsigned long long b) {
    asm("fma.rn.f32x2 %0, %1, %2, %0;" : "+l"(d) : "l"(a), "l"(b));
}
__device__ __forceinline__ unsigned long long pack2(float v) {
    unsigned long long r;
    asm("mov.b64 %0, {%1, %1};" : "=l"(r) : "f"(v));
    return r;
}
__device__ __forceinline__ void add2(unsigned long long& d, unsigned long long a) {
    asm("add.rn.f32x2 %0, %0, %1;" : "+l"(d) : "l"(a));
}
union U2 { float2 f; unsigned long long u; };
union U4 { float4 f; ulonglong2 u; };
__device__ __forceinline__ float usum(unsigned long long v) {
    U2 x; x.u = v; return x.f.x + x.f.y;
}
// fast sigmoid / tanh via MUFU
__device__ __forceinline__ float fsig(float x) {
    return __fdividef(1.f, 1.f + __expf(-x));
}
__device__ __forceinline__ float ftanh(float x) {
    return __fdividef(2.f, 1.f + __expf(-2.f * x)) - 1.f;
}

// ============================================================================
// Kernel 1: Gx = emb[x] . WxT + bias, output TRANSPOSED as [t][g][b].
//   128x128 tile, BK=16, 8x8/thread, scalar FFMA (round-4 proven body).
// ============================================================================
__global__ __launch_bounds__(256) void gx_kernel(
    const int* __restrict__ x, const float* __restrict__ emb,
    const float* __restrict__ W, const float* __restrict__ bias)
{
    __shared__ float As[16][128];
    __shared__ float Bs[16][128];
    __shared__ int   tok[128];

    const int tid = threadIdx.x;
    const int m0 = blockIdx.x * 128;
    const int n0 = blockIdx.y * 128;

    if (tid < 128) {
        int m = m0 + tid;
        tok[tid] = x[(m & 63) * SEQ + (m >> 6)];
    }
    __syncthreads();

    const int lm = tid & 127, lq = tid >> 7;
    const int tx = tid & 15,  ty = tid >> 4;

    float acc[8][8];
#pragma unroll
    for (int i = 0; i < 8; i++)
#pragma unroll
        for (int jj = 0; jj < 8; jj++) acc[i][jj] = 0.f;

    float4 ra0, ra1, rb0, rb1;
    {
        const float* arow = emb + (size_t)tok[lm] * EMBD;
        ra0 = *(const float4*)(arow + lq * 4);
        ra1 = *(const float4*)(arow + 8 + lq * 4);
        const float* brow = W + (size_t)(n0 + lm) * WROW;
        rb0 = *(const float4*)(brow + lq * 4);
        rb1 = *(const float4*)(brow + 8 + lq * 4);
    }

    for (int kt = 0; kt < 16; kt++) {
        As[lq * 4 + 0][lm] = ra0.x; As[lq * 4 + 1][lm] = ra0.y;
        As[lq * 4 + 2][lm] = ra0.z; As[lq * 4 + 3][lm] = ra0.w;
        As[8 + lq * 4 + 0][lm] = ra1.x; As[8 + lq * 4 + 1][lm] = ra1.y;
        As[8 + lq * 4 + 2][lm] = ra1.z; As[8 + lq * 4 + 3][lm] = ra1.w;
        Bs[lq * 4 + 0][lm] = rb0.x; Bs[lq * 4 + 1][lm] = rb0.y;
        Bs[lq * 4 + 2][lm] = rb0.z; Bs[lq * 4 + 3][lm] = rb0.w;
        Bs[8 + lq * 4 + 0][lm] = rb1.x; Bs[8 + lq * 4 + 1][lm] = rb1.y;
        Bs[8 + lq * 4 + 2][lm] = rb1.z; Bs[8 + lq * 4 + 3][lm] = rb1.w;
        __syncthreads();

        if (kt < 15) {
            int k0 = (kt + 1) * 16;
            const float* arow = emb + (size_t)tok[lm] * EMBD + k0;
            ra0 = *(const float4*)(arow + lq * 4);
            ra1 = *(const float4*)(arow + 8 + lq * 4);
            const float* brow = W + (size_t)(n0 + lm) * WROW + k0;
            rb0 = *(const float4*)(brow + lq * 4);
            rb1 = *(const float4*)(brow + 8 + lq * 4);
        }

#pragma unroll
        for (int k = 0; k < 16; k++) {
            float4 aL = *(const float4*)&As[k][ty * 4];
            float4 aH = *(const float4*)&As[k][64 + ty * 4];
            float4 bL = *(const float4*)&Bs[k][tx * 4];
            float4 bH = *(const float4*)&Bs[k][64 + tx * 4];
            float av[8] = {aL.x, aL.y, aL.z, aL.w, aH.x, aH.y, aH.z, aH.w};
            float bv[8] = {bL.x, bL.y, bL.z, bL.w, bH.x, bH.y, bH.z, bH.w};
#pragma unroll
            for (int i = 0; i < 8; i++)
#pragma unroll
                for (int jj = 0; jj < 8; jj++)
                    acc[i][jj] = fmaf(av[i], bv[jj], acc[i][jj]);
        }
        __syncthreads();
    }

    {
        float4 biL = *(const float4*)(bias + n0 + tx * 4);
        float4 biH = *(const float4*)(bias + n0 + 64 + tx * 4);
        float bl[8] = {biL.x, biL.y, biL.z, biL.w, biH.x, biH.y, biH.z, biH.w};
#pragma unroll
        for (int r = 0; r < 8; r++)
#pragma unroll
            for (int cc = 0; cc < 8; cc++) acc[r][cc] += bl[cc];
    }

    // transposed store: 8 stages of 16 columns through As (16x128 floats)
    float* T = &As[0][0];
    for (int s = 0; s < 8; s++) {
        __syncthreads();
        int txg = s & 3;
        int jbase = (s < 4) ? 0 : 4;
        if ((tx >> 2) == txg) {
#pragma unroll
            for (int q = 0; q < 4; q++) {
                int cl = (tx & 3) * 4 + q;
#pragma unroll
                for (int r = 0; r < 8; r++) {
                    int m_loc = (r >> 2) * 64 + ty * 4 + (r & 3);
                    T[cl * 128 + m_loc] = acc[r][jbase + q];
                }
            }
        }
        __syncthreads();
#pragma unroll
        for (int w = 0; w < 2; w++) {
            int v = tid + w * 256;
            int row = v >> 4;
            int within = v & 15;
            int cl = row >> 1, tl = row & 1;
            float4 val = *(float4*)&T[cl * 128 + tl * 64 + within * 4];
            int t = (m0 >> 6) + tl;
            int gcol = n0 + s * 16 + cl;
            *(float4*)&g_Gx[((size_t)t * NG + gcol) * BATCH + within * 4] = val;
        }
    }
}

// ============================================================================
// Kernel 2: persistent LSTM recurrence. 128 CTAs x 512 threads (16 warps,
//   4/SMSP). Thread = (b, jl, kh): one batch, j = 4*bx+jl, k-half kh.
//   k-paired f32x2; weight rows smem-broadcast; single-shot FULL h restage;
//   2-way k reduction through smem.
// ============================================================================
__global__ __launch_bounds__(512, 1) void lstm_kernel(const float* __restrict__ W)
{
    extern __shared__ float smem[];
    float* hs = smem;                                  // 64 x 516
    float* ws = smem + BATCH * HS_STRIDE;              // 16 x 512
    unsigned long long* red =
        (unsigned long long*)(smem + BATCH * HS_STRIDE + 16 * HID); // 256 x 4

    const int tid  = threadIdx.x;
    const int bx   = blockIdx.x;
    const int warp = tid >> 5;
    const int b    = (tid & 31) | ((warp & 1) << 5);
    const int jl   = (warp >> 1) & 3;
    const int kh   = warp >> 3;            // 0 or 1
    const int j    = bx * 4 + jl;
    const unsigned base = g_epoch;

    for (int i = tid; i < 16 * HID; i += 512) {
        int row = i >> 9;
        int k   = i & 511;
        int jlw = row >> 2, g = row & 3;
        ws[i] = W[(size_t)(g * HID + bx * 4 + jlw) * WROW + EMBD + k];
    }
    for (int i = bx * 512 + tid; i < BATCH * HID; i += NCTA * 512)
        g_h[0][i] = 0.f;

    gbar(bx, tid, base + 1);

    const float4* wf4 = (const float4*)(ws + (jl * 4 + 0) * HID);
    const float4* wi4 = (const float4*)(ws + (jl * 4 + 1) * HID);
    const float4* wo4 = (const float4*)(ws + (jl * 4 + 2) * HID);
    const float4* wc4 = (const float4*)(ws + (jl * 4 + 3) * HID);
    const float4* hp  = (const float4*)(hs + b * HS_STRIDE);
    const int hq0 = kh * 64;               // this half's first f4 index

    float C = 0.f, hv = 0.f;
    int cur = 0;

    for (int t = 0; t < SEQ; t++) {
        // gate biases for finalizers
        float gf, gi, go, gc;
        if (kh == 0) {
            const float* gxt = g_Gx + (size_t)t * NG * BATCH;
            gf = __ldcg(gxt + (size_t)(0 * HID + j) * BATCH + b);
            gi = __ldcg(gxt + (size_t)(1 * HID + j) * BATCH + b);
            go = __ldcg(gxt + (size_t)(2 * HID + j) * BATCH + b);
            gc = __ldcg(gxt + (size_t)(3 * HID + j) * BATCH + b);
        }

        // single-shot FULL restage: 8192 f4 over 512 threads (16 each)
        {
            const float4* src = (const float4*)g_h[cur];   // rows of 128 f4
            float4* dst = (float4*)hs;                     // rows of 129 f4
#pragma unroll
            for (int i = 0; i < 16; i++) {
                int e = tid + (i << 9);
                int bb = e >> 7, c4 = e & 127;
                dst[bb * 129 + c4] = __ldcg(src + bb * 128 + c4);
            }
        }
        __syncthreads();

        unsigned long long fa = 0, ia = 0, oa = 0, ca = 0;
#pragma unroll 8
        for (int it = 0; it < 64; it++) {
            int idx = hq0 + it;
            U4 hh, wf, wi, wo, wc;
            hh.f = hp[idx];
            wf.f = wf4[idx]; wi.f = wi4[idx];
            wo.f = wo4[idx]; wc.f = wc4[idx];
            fma2(fa, hh.u.x, wf.u.x); fma2(fa, hh.u.y, wf.u.y);
            fma2(ia, hh.u.x, wi.u.x); fma2(ia, hh.u.y, wi.u.y);
            fma2(oa, hh.u.x, wo.u.x); fma2(oa, hh.u.y, wo.u.y);
            fma2(ca, hh.u.x, wc.u.x); fma2(ca, hh.u.y, wc.u.y);
        }

        if (kh) {
            unsigned long long* r = red + (tid - 256) * 4;
            r[0] = fa; r[1] = ia; r[2] = oa; r[3] = ca;
        }
        __syncthreads();
        if (!kh) {
            const unsigned long long* r = red + tid * 4;
            add2(fa, r[0]); add2(ia, r[1]); add2(oa, r[2]); add2(ca, r[3]);

            float af = usum(fa) + gf, ai = usum(ia) + gi;
            float ao = usum(oa) + go, ac = usum(ca) + gc;
            float F = fsig(af), I = fsig(ai), O = fsig(ao);
            C = F * C + I * ftanh(ac);
            hv = O * ftanh(C);
            g_h[cur ^ 1][b * HID + j] = hv;
        }

        gbar(bx, tid, base + 2 + t);
        cur ^= 1;
    }

    if (!kh) g_hbt[(size_t)j * BATCH + b] = hv;    // [k][b] for fc
    if (bx == 0 && tid == 0) g_epoch = base + SEQ + 8;
}

// ============================================================================
// Kernel 3: out[b][n] = h[b] . fc_weight[n] + fc_bias[n]
//   h staged in smem as [k][b] padded rows; f32x2 over batch pairs.
// ============================================================================
__global__ __launch_bounds__(256, 1) void fc_kernel(
    const float* __restrict__ fcw, const float* __restrict__ fcb,
    float* __restrict__ out)
{
    extern __shared__ float hb2[];   // 512 rows x 68 floats
    const int tid = threadIdx.x;
    for (int i = tid; i < HID * 16; i += 256) {
        int k = i >> 4, q = i & 15;
        ((float4*)(hb2 + k * 68))[q] = ((const float4*)g_hbt)[i];
    }
    __syncthreads();

    const int warp = tid >> 5, lane = tid & 31;
    const int wglobal = blockIdx.x * 8 + warp;
    const int nw = gridDim.x * 8;

    for (int n = wglobal; n < NCLS; n += nw) {
        unsigned long long acc[32];
#pragma unroll
        for (int i = 0; i < 32; i++) acc[i] = 0ull;
        const float* wrow = fcw + (size_t)n * HID;
#pragma unroll
        for (int kk = 0; kk < 16; kk++) {
            int k = kk * 32 + lane;
            unsigned long long ww = pack2(wrow[k]);
            const float4* hrow = (const float4*)(hb2 + k * 68);
#pragma unroll
            for (int q = 0; q < 16; q++) {
                U4 hh; hh.f = hrow[q];
                fma2(acc[2 * q],     ww, hh.u.x);
                fma2(acc[2 * q + 1], ww, hh.u.y);
            }
        }
        float bias = fcb[n];
#pragma unroll
        for (int p = 0; p < 32; p++) {
            unsigned long long v = acc[p];
            add2(v, __shfl_xor_sync(0xffffffffu, v, 16));
            add2(v, __shfl_xor_sync(0xffffffffu, v, 8));
            add2(v, __shfl_xor_sync(0xffffffffu, v, 4));
            add2(v, __shfl_xor_sync(0xffffffffu, v, 2));
            add2(v, __shfl_xor_sync(0xffffffffu, v, 1));
            if (lane == 0) {
                U2 u; u.u = v;
                out[(size_t)(2 * p) * NCLS + n]     = u.f.x + bias;
                out[(size_t)(2 * p + 1) * NCLS + n] = u.f.y + bias;
            }
        }
    }
}

// ============================================================================
extern "C" void kernel_launch(void* const* d_in, const int* in_sizes, int n_in,
                              void* d_out, int out_size)
{
    const int*   x   = (const int*)d_in[0];
    const float* emb = (const float*)d_in[1];
    const float* W   = (const float*)d_in[2];
    const float* Wb  = (const float*)d_in[3];
    const float* fcw = (const float*)d_in[4];
    const float* fcb = (const float*)d_in[5];
    float* out = (float*)d_out;

    // hs 33024 f + ws 8192 f + red 1024 u64 (2048 f)  = 43264 f = 173056 B
    static const size_t lstm_smem =
        (size_t)(BATCH * HS_STRIDE + 16 * HID + 2048) * 4;
    static const size_t fc_smem = (size_t)HID * 68 * 4;      // 139264
    cudaFuncSetAttribute(lstm_kernel, cudaFuncAttributeMaxDynamicSharedMemorySize,
                         (int)lstm_smem);
    cudaFuncSetAttribute(fc_kernel, cudaFuncAttributeMaxDynamicSharedMemorySize,
                         (int)fc_smem);

    dim3 g1(SEQ * BATCH / 128, NG / 128);
    gx_kernel<<<g1, 256>>>(x, emb, W, Wb);

    lstm_kernel<<<NCTA, 512, lstm_smem>>>(W);

    fc_kernel<<<148, 256, fc_smem>>>(fcw, fcb, out);
}

// round 9
// speedup vs baseline: 1.7602x; 1.2212x over previous
#include <cuda_runtime.h>
#include <math.h>

#define EMBD 256
#define HID  512
#define BATCH 64
#define SEQ  512
#define NG   2048      // 4*HID
#define WROW 768       // EMB+HID
#define NCLS 50257
#define NCTA 128
#define HS_STRIDE 516  // padded floats per h row in smem (129 float4)

// ---------------- scratch (static device globals; no cudaMalloc allowed) ----
__device__ float g_Gx[(size_t)SEQ * NG * BATCH];   // [t][g][b]  (transposed)
__device__ float g_h[2][BATCH * HID];              // [b][k]
__device__ float g_hbt[HID * BATCH];               // final hidden, [k][b]
__device__ volatile unsigned g_arrive[NCTA];
__device__ volatile unsigned g_release;
__device__ unsigned g_epoch;                       // bumped each launch (replay-safe)

// ---------------- flag-tree grid barrier (all 128 CTAs resident) ------------
__device__ __forceinline__ void gbar(int bx, int tid, unsigned gen) {
    __threadfence();
    __syncthreads();
    if (bx == 0) {
        if (tid > 0 && tid < NCTA) {
            while (g_arrive[tid] < gen) { }
        }
        __syncthreads();
        if (tid == 0) { __threadfence(); g_release = gen; }
    } else {
        if (tid == 0) {
            g_arrive[bx] = gen;
            while (g_release < gen) { }
        }
    }
    __syncthreads();
}

// ---------------- packed f32x2 helpers --------------------------------------
__device__ __forceinline__ void fma2(unsigned long long& d,
                                     unsigned long long a,
                                     unsigned long long b) {
    asm("fma.rn.f32x2 %0, %1, %2, %0;" : "+l"(d) : "l"(a), "l"(b));
}
__device__ __forceinline__ unsigned long long pack2(float v) {
    unsigned long long r;
    asm("mov.b64 %0, {%1, %1};" : "=l"(r) : "f"(v));
    return r;
}
__device__ __forceinline__ void add2(unsigned long long& d, unsigned long long a) {
    asm("add.rn.f32x2 %0, %0, %1;" : "+l"(d) : "l"(a));
}
union U2 { float2 f; unsigned long long u; };
union U4 { float4 f; ulonglong2 u; };
__device__ __forceinline__ float usum(unsigned long long v) {
    U2 x; x.u = v; return x.f.x + x.f.y;
}
// fast sigmoid / tanh via MUFU
__device__ __forceinline__ float fsig(float x) {
    return __fdividef(1.f, 1.f + __expf(-x));
}
__device__ __forceinline__ float ftanh(float x) {
    return __fdividef(2.f, 1.f + __expf(-2.f * x)) - 1.f;
}

// ============================================================================
// Kernel 1: Gx = emb[x] . WxT + bias, output TRANSPOSED as [t][g][b].
//   128x128 tile, BK=16, 8x8/thread, scalar FFMA (proven body).
// ============================================================================
__global__ __launch_bounds__(256) void gx_kernel(
    const int* __restrict__ x, const float* __restrict__ emb,
    const float* __restrict__ W, const float* __restrict__ bias)
{
    __shared__ float As[16][128];
    __shared__ float Bs[16][128];
    __shared__ int   tok[128];

    const int tid = threadIdx.x;
    const int m0 = blockIdx.x * 128;
    const int n0 = blockIdx.y * 128;

    if (tid < 128) {
        int m = m0 + tid;
        tok[tid] = x[(m & 63) * SEQ + (m >> 6)];
    }
    __syncthreads();

    const int lm = tid & 127, lq = tid >> 7;
    const int tx = tid & 15,  ty = tid >> 4;

    float acc[8][8];
#pragma unroll
    for (int i = 0; i < 8; i++)
#pragma unroll
        for (int jj = 0; jj < 8; jj++) acc[i][jj] = 0.f;

    float4 ra0, ra1, rb0, rb1;
    {
        const float* arow = emb + (size_t)tok[lm] * EMBD;
        ra0 = *(const float4*)(arow + lq * 4);
        ra1 = *(const float4*)(arow + 8 + lq * 4);
        const float* brow = W + (size_t)(n0 + lm) * WROW;
        rb0 = *(const float4*)(brow + lq * 4);
        rb1 = *(const float4*)(brow + 8 + lq * 4);
    }

    for (int kt = 0; kt < 16; kt++) {
        As[lq * 4 + 0][lm] = ra0.x; As[lq * 4 + 1][lm] = ra0.y;
        As[lq * 4 + 2][lm] = ra0.z; As[lq * 4 + 3][lm] = ra0.w;
        As[8 + lq * 4 + 0][lm] = ra1.x; As[8 + lq * 4 + 1][lm] = ra1.y;
        As[8 + lq * 4 + 2][lm] = ra1.z; As[8 + lq * 4 + 3][lm] = ra1.w;
        Bs[lq * 4 + 0][lm] = rb0.x; Bs[lq * 4 + 1][lm] = rb0.y;
        Bs[lq * 4 + 2][lm] = rb0.z; Bs[lq * 4 + 3][lm] = rb0.w;
        Bs[8 + lq * 4 + 0][lm] = rb1.x; Bs[8 + lq * 4 + 1][lm] = rb1.y;
        Bs[8 + lq * 4 + 2][lm] = rb1.z; Bs[8 + lq * 4 + 3][lm] = rb1.w;
        __syncthreads();

        if (kt < 15) {
            int k0 = (kt + 1) * 16;
            const float* arow = emb + (size_t)tok[lm] * EMBD + k0;
            ra0 = *(const float4*)(arow + lq * 4);
            ra1 = *(const float4*)(arow + 8 + lq * 4);
            const float* brow = W + (size_t)(n0 + lm) * WROW + k0;
            rb0 = *(const float4*)(brow + lq * 4);
            rb1 = *(const float4*)(brow + 8 + lq * 4);
        }

#pragma unroll
        for (int k = 0; k < 16; k++) {
            float4 aL = *(const float4*)&As[k][ty * 4];
            float4 aH = *(const float4*)&As[k][64 + ty * 4];
            float4 bL = *(const float4*)&Bs[k][tx * 4];
            float4 bH = *(const float4*)&Bs[k][64 + tx * 4];
            float av[8] = {aL.x, aL.y, aL.z, aL.w, aH.x, aH.y, aH.z, aH.w};
            float bv[8] = {bL.x, bL.y, bL.z, bL.w, bH.x, bH.y, bH.z, bH.w};
#pragma unroll
            for (int i = 0; i < 8; i++)
#pragma unroll
                for (int jj = 0; jj < 8; jj++)
                    acc[i][jj] = fmaf(av[i], bv[jj], acc[i][jj]);
        }
        __syncthreads();
    }

    {
        float4 biL = *(const float4*)(bias + n0 + tx * 4);
        float4 biH = *(const float4*)(bias + n0 + 64 + tx * 4);
        float bl[8] = {biL.x, biL.y, biL.z, biL.w, biH.x, biH.y, biH.z, biH.w};
#pragma unroll
        for (int r = 0; r < 8; r++)
#pragma unroll
            for (int cc = 0; cc < 8; cc++) acc[r][cc] += bl[cc];
    }

    // transposed store: 8 stages of 16 columns through As (16x128 floats)
    float* T = &As[0][0];
    for (int s = 0; s < 8; s++) {
        __syncthreads();
        int txg = s & 3;
        int jbase = (s < 4) ? 0 : 4;
        if ((tx >> 2) == txg) {
#pragma unroll
            for (int q = 0; q < 4; q++) {
                int cl = (tx & 3) * 4 + q;
#pragma unroll
                for (int r = 0; r < 8; r++) {
                    int m_loc = (r >> 2) * 64 + ty * 4 + (r & 3);
                    T[cl * 128 + m_loc] = acc[r][jbase + q];
                }
            }
        }
        __syncthreads();
#pragma unroll
        for (int w = 0; w < 2; w++) {
            int v = tid + w * 256;
            int row = v >> 4;
            int within = v & 15;
            int cl = row >> 1, tl = row & 1;
            float4 val = *(float4*)&T[cl * 128 + tl * 64 + within * 4];
            int t = (m0 >> 6) + tl;
            int gcol = n0 + s * 16 + cl;
            *(float4*)&g_Gx[((size_t)t * NG + gcol) * BATCH + within * 4] = val;
        }
    }
}

// ============================================================================
// Kernel 2: persistent LSTM recurrence. 128 CTAs x 512 threads (16 warps,
//   4/SMSP). Thread = (lane l -> batches l and l+32, jl = warp&3,
//   kq = warp>>2 in 0..3 -> k-quarter of 32 f4). One weight fetch feeds two
//   batches -> crossbar 6144 cyc/SM/step. 4-way k reduction through smem.
// ============================================================================
__global__ __launch_bounds__(512, 1) void lstm_kernel(const float* __restrict__ W)
{
    extern __shared__ float smem[];
    float* hs = smem;                                  // 64 x 516
    float* ws = smem + BATCH * HS_STRIDE;              // 16 x 512
    unsigned long long* red =
        (unsigned long long*)(smem + BATCH * HS_STRIDE + 16 * HID); // 3*128*9 u64

    const int tid  = threadIdx.x;
    const int bx   = blockIdx.x;
    const int l    = tid & 31;             // b0 = l, b1 = l + 32
    const int warp = tid >> 5;
    const int jl   = warp & 3;
    const int kq   = warp >> 2;            // 0..3
    const int j    = bx * 4 + jl;
    const unsigned base = g_epoch;

    for (int i = tid; i < 16 * HID; i += 512) {
        int row = i >> 9;
        int k   = i & 511;
        int jlw = row >> 2, g = row & 3;
        ws[i] = W[(size_t)(g * HID + bx * 4 + jlw) * WROW + EMBD + k];
    }
    for (int i = bx * 512 + tid; i < BATCH * HID; i += NCTA * 512)
        g_h[0][i] = 0.f;

    gbar(bx, tid, base + 1);

    const float4* wf4 = (const float4*)(ws + (jl * 4 + 0) * HID) + kq * 32;
    const float4* wi4 = (const float4*)(ws + (jl * 4 + 1) * HID) + kq * 32;
    const float4* wo4 = (const float4*)(ws + (jl * 4 + 2) * HID) + kq * 32;
    const float4* wc4 = (const float4*)(ws + (jl * 4 + 3) * HID) + kq * 32;
    const float4* hp0 = (const float4*)(hs + l * HS_STRIDE) + kq * 32;
    const float4* hp1 = (const float4*)(hs + (l + 32) * HS_STRIDE) + kq * 32;

    float C0 = 0.f, C1 = 0.f, hv0 = 0.f, hv1 = 0.f;
    int cur = 0;

    for (int t = 0; t < SEQ; t++) {
        // gate biases (kq==0 finalizers only; both batches)
        float gf0, gi0, go0, gc0, gf1, gi1, go1, gc1;
        if (kq == 0) {
            const float* gxt = g_Gx + (size_t)t * NG * BATCH;
            gf0 = __ldcg(gxt + (size_t)(0 * HID + j) * BATCH + l);
            gi0 = __ldcg(gxt + (size_t)(1 * HID + j) * BATCH + l);
            go0 = __ldcg(gxt + (size_t)(2 * HID + j) * BATCH + l);
            gc0 = __ldcg(gxt + (size_t)(3 * HID + j) * BATCH + l);
            gf1 = __ldcg(gxt + (size_t)(0 * HID + j) * BATCH + l + 32);
            gi1 = __ldcg(gxt + (size_t)(1 * HID + j) * BATCH + l + 32);
            go1 = __ldcg(gxt + (size_t)(2 * HID + j) * BATCH + l + 32);
            gc1 = __ldcg(gxt + (size_t)(3 * HID + j) * BATCH + l + 32);
        }

        // single-shot FULL restage: 8192 f4 over 512 threads; batch all LDGs
        // (MLP=16) then all STSs.
        {
            const float4* src = (const float4*)g_h[cur];   // rows of 128 f4
            float4* dst = (float4*)hs;                     // rows of 129 f4
            float4 rr[16];
#pragma unroll
            for (int i = 0; i < 16; i++) {
                int e = tid + (i << 9);
                rr[i] = __ldcg(src + (e >> 7) * 128 + (e & 127));
            }
#pragma unroll
            for (int i = 0; i < 16; i++) {
                int e = tid + (i << 9);
                dst[(e >> 7) * 129 + (e & 127)] = rr[i];
            }
        }
        __syncthreads();

        unsigned long long f0 = 0, i0 = 0, o0 = 0, c0 = 0;
        unsigned long long f1 = 0, i1 = 0, o1 = 0, c1 = 0;
#pragma unroll 8
        for (int it = 0; it < 32; it++) {
            U4 wf, wi, wo, wc, ha, hb;
            ha.f = hp0[it]; hb.f = hp1[it];
            wf.f = wf4[it]; wi.f = wi4[it];
            wo.f = wo4[it]; wc.f = wc4[it];
            fma2(f0, ha.u.x, wf.u.x); fma2(f0, ha.u.y, wf.u.y);
            fma2(i0, ha.u.x, wi.u.x); fma2(i0, ha.u.y, wi.u.y);
            fma2(o0, ha.u.x, wo.u.x); fma2(o0, ha.u.y, wo.u.y);
            fma2(c0, ha.u.x, wc.u.x); fma2(c0, ha.u.y, wc.u.y);
            fma2(f1, hb.u.x, wf.u.x); fma2(f1, hb.u.y, wf.u.y);
            fma2(i1, hb.u.x, wi.u.x); fma2(i1, hb.u.y, wi.u.y);
            fma2(o1, hb.u.x, wo.u.x); fma2(o1, hb.u.y, wo.u.y);
            fma2(c1, hb.u.x, wc.u.x); fma2(c1, hb.u.y, wc.u.y);
        }

        if (kq) {
            unsigned long long* r = red + ((size_t)(kq - 1) * 128 + jl * 32 + l) * 9;
            r[0] = f0; r[1] = i0; r[2] = o0; r[3] = c0;
            r[4] = f1; r[5] = i1; r[6] = o1; r[7] = c1;
        }
        __syncthreads();
        if (kq == 0) {
#pragma unroll
            for (int s = 0; s < 3; s++) {
                const unsigned long long* r =
                    red + ((size_t)s * 128 + jl * 32 + l) * 9;
                add2(f0, r[0]); add2(i0, r[1]); add2(o0, r[2]); add2(c0, r[3]);
                add2(f1, r[4]); add2(i1, r[5]); add2(o1, r[6]); add2(c1, r[7]);
            }
            {
                float af = usum(f0) + gf0, ai = usum(i0) + gi0;
                float ao = usum(o0) + go0, ac = usum(c0) + gc0;
                float F = fsig(af), I = fsig(ai), O = fsig(ao);
                C0 = F * C0 + I * ftanh(ac);
                hv0 = O * ftanh(C0);
            }
            {
                float af = usum(f1) + gf1, ai = usum(i1) + gi1;
                float ao = usum(o1) + go1, ac = usum(c1) + gc1;
                float F = fsig(af), I = fsig(ai), O = fsig(ao);
                C1 = F * C1 + I * ftanh(ac);
                hv1 = O * ftanh(C1);
            }
            g_h[cur ^ 1][l * HID + j]        = hv0;
            g_h[cur ^ 1][(l + 32) * HID + j] = hv1;
        }

        gbar(bx, tid, base + 2 + t);
        cur ^= 1;
    }

    if (kq == 0) {
        g_hbt[(size_t)j * BATCH + l]      = hv0;
        g_hbt[(size_t)j * BATCH + l + 32] = hv1;
    }
    if (bx == 0 && tid == 0) g_epoch = base + SEQ + 8;
}

// ============================================================================
// Kernel 3: out[b][n] = h[b] . fc_weight[n] + fc_bias[n]
//   h staged in smem as [k][b] padded rows; f32x2 over batch pairs.
// ============================================================================
__global__ __launch_bounds__(256, 1) void fc_kernel(
    const float* __restrict__ fcw, const float* __restrict__ fcb,
    float* __restrict__ out)
{
    extern __shared__ float hb2[];   // 512 rows x 68 floats
    const int tid = threadIdx.x;
    for (int i = tid; i < HID * 16; i += 256) {
        int k = i >> 4, q = i & 15;
        ((float4*)(hb2 + k * 68))[q] = ((const float4*)g_hbt)[i];
    }
    __syncthreads();

    const int warp = tid >> 5, lane = tid & 31;
    const int wglobal = blockIdx.x * 8 + warp;
    const int nw = gridDim.x * 8;

    for (int n = wglobal; n < NCLS; n += nw) {
        unsigned long long acc[32];
#pragma unroll
        for (int i = 0; i < 32; i++) acc[i] = 0ull;
        const float* wrow = fcw + (size_t)n * HID;
#pragma unroll
        for (int kk = 0; kk < 16; kk++) {
            int k = kk * 32 + lane;
            unsigned long long ww = pack2(wrow[k]);
            const float4* hrow = (const float4*)(hb2 + k * 68);
#pragma unroll
            for (int q = 0; q < 16; q++) {
                U4 hh; hh.f = hrow[q];
                fma2(acc[2 * q],     ww, hh.u.x);
                fma2(acc[2 * q + 1], ww, hh.u.y);
            }
        }
        float bias = fcb[n];
#pragma unroll
        for (int p = 0; p < 32; p++) {
            unsigned long long v = acc[p];
            add2(v, __shfl_xor_sync(0xffffffffu, v, 16));
            add2(v, __shfl_xor_sync(0xffffffffu, v, 8));
            add2(v, __shfl_xor_sync(0xffffffffu, v, 4));
            add2(v, __shfl_xor_sync(0xffffffffu, v, 2));
            add2(v, __shfl_xor_sync(0xffffffffu, v, 1));
            if (lane == 0) {
                U2 u; u.u = v;
                out[(size_t)(2 * p) * NCLS + n]     = u.f.x + bias;
                out[(size_t)(2 * p + 1) * NCLS + n] = u.f.y + bias;
            }
        }
    }
}

// ============================================================================
extern "C" void kernel_launch(void* const* d_in, const int* in_sizes, int n_in,
                              void* d_out, int out_size)
{
    const int*   x   = (const int*)d_in[0];
    const float* emb = (const float*)d_in[1];
    const float* W   = (const float*)d_in[2];
    const float* Wb  = (const float*)d_in[3];
    const float* fcw = (const float*)d_in[4];
    const float* fcb = (const float*)d_in[5];
    float* out = (float*)d_out;

    // hs 33024 f + ws 8192 f = 164864 B ; red 3*128*9 u64 = 27648 B
    static const size_t lstm_smem =
        (size_t)(BATCH * HS_STRIDE + 16 * HID) * 4 + 3 * 128 * 9 * 8;
    static const size_t fc_smem = (size_t)HID * 68 * 4;      // 139264
    cudaFuncSetAttribute(lstm_kernel, cudaFuncAttributeMaxDynamicSharedMemorySize,
                         (int)lstm_smem);
    cudaFuncSetAttribute(fc_kernel, cudaFuncAttributeMaxDynamicSharedMemorySize,
                         (int)fc_smem);

    dim3 g1(SEQ * BATCH / 128, NG / 128);
    gx_kernel<<<g1, 256>>>(x, emb, W, Wb);

    lstm_kernel<<<NCTA, 512, lstm_smem>>>(W);

    fc_kernel<<<148, 256, fc_smem>>>(fcw, fcb, out);
}

// round 10
// speedup vs baseline: 1.7867x; 1.0151x over previous
#include <cuda_runtime.h>
#include <math.h>

#define EMBD 256
#define HID  512
#define BATCH 64
#define SEQ  512
#define NG   2048      // 4*HID
#define WROW 768       // EMB+HID
#define NCLS 50257
#define NCTA 128
#define HS_STRIDE 516  // padded floats per h row in smem (129 float4)

// ---------------- scratch (static device globals; no cudaMalloc allowed) ----
__device__ float g_Gx[(size_t)SEQ * NG * BATCH];   // [t][g][b]  (transposed)
__device__ float g_h[2][BATCH * HID];              // [b][k]
__device__ float g_hbt[HID * BATCH];               // final hidden, [k][b]
__device__ volatile unsigned g_arrive[NCTA];
__device__ volatile unsigned g_release;
__device__ unsigned g_epoch;                       // bumped each launch (replay-safe)

// ---------------- flag-tree grid barrier (all 128 CTAs resident) ------------
__device__ __forceinline__ void gbar(int bx, int tid, unsigned gen) {
    __threadfence();
    __syncthreads();
    if (bx == 0) {
        if (tid > 0 && tid < NCTA) {
            while (g_arrive[tid] < gen) { }
        }
        __syncthreads();
        if (tid == 0) { __threadfence(); g_release = gen; }
    } else {
        if (tid == 0) {
            g_arrive[bx] = gen;
            while (g_release < gen) { }
        }
    }
    __syncthreads();
}

// ---------------- packed f32x2 helpers --------------------------------------
__device__ __forceinline__ void fma2(unsigned long long& d,
                                     unsigned long long a,
                                     unsigned long long b) {
    asm("fma.rn.f32x2 %0, %1, %2, %0;" : "+l"(d) : "l"(a), "l"(b));
}
__device__ __forceinline__ unsigned long long pack2(float v) {
    unsigned long long r;
    asm("mov.b64 %0, {%1, %1};" : "=l"(r) : "f"(v));
    return r;
}
__device__ __forceinline__ void add2(unsigned long long& d, unsigned long long a) {
    asm("add.rn.f32x2 %0, %0, %1;" : "+l"(d) : "l"(a));
}
union U2 { float2 f; unsigned long long u; };
union U4 { float4 f; ulonglong2 u; };
__device__ __forceinline__ float usum(unsigned long long v) {
    U2 x; x.u = v; return x.f.x + x.f.y;
}
// fast sigmoid / tanh via MUFU
__device__ __forceinline__ float fsig(float x) {
    return __fdividef(1.f, 1.f + __expf(-x));
}
__device__ __forceinline__ float ftanh(float x) {
    return __fdividef(2.f, 1.f + __expf(-2.f * x)) - 1.f;
}

// ============================================================================
// Kernel 1: Gx = emb[x] . WxT + bias, output TRANSPOSED as [t][g][b].
//   128x128 tile, BK=16, 8x8/thread, scalar FFMA (proven body).
// ============================================================================
__global__ __launch_bounds__(256) void gx_kernel(
    const int* __restrict__ x, const float* __restrict__ emb,
    const float* __restrict__ W, const float* __restrict__ bias)
{
    __shared__ float As[16][128];
    __shared__ float Bs[16][128];
    __shared__ int   tok[128];

    const int tid = threadIdx.x;
    const int m0 = blockIdx.x * 128;
    const int n0 = blockIdx.y * 128;

    if (tid < 128) {
        int m = m0 + tid;
        tok[tid] = x[(m & 63) * SEQ + (m >> 6)];
    }
    __syncthreads();

    const int lm = tid & 127, lq = tid >> 7;
    const int tx = tid & 15,  ty = tid >> 4;

    float acc[8][8];
#pragma unroll
    for (int i = 0; i < 8; i++)
#pragma unroll
        for (int jj = 0; jj < 8; jj++) acc[i][jj] = 0.f;

    float4 ra0, ra1, rb0, rb1;
    {
        const float* arow = emb + (size_t)tok[lm] * EMBD;
        ra0 = *(const float4*)(arow + lq * 4);
        ra1 = *(const float4*)(arow + 8 + lq * 4);
        const float* brow = W + (size_t)(n0 + lm) * WROW;
        rb0 = *(const float4*)(brow + lq * 4);
        rb1 = *(const float4*)(brow + 8 + lq * 4);
    }

    for (int kt = 0; kt < 16; kt++) {
        As[lq * 4 + 0][lm] = ra0.x; As[lq * 4 + 1][lm] = ra0.y;
        As[lq * 4 + 2][lm] = ra0.z; As[lq * 4 + 3][lm] = ra0.w;
        As[8 + lq * 4 + 0][lm] = ra1.x; As[8 + lq * 4 + 1][lm] = ra1.y;
        As[8 + lq * 4 + 2][lm] = ra1.z; As[8 + lq * 4 + 3][lm] = ra1.w;
        Bs[lq * 4 + 0][lm] = rb0.x; Bs[lq * 4 + 1][lm] = rb0.y;
        Bs[lq * 4 + 2][lm] = rb0.z; Bs[lq * 4 + 3][lm] = rb0.w;
        Bs[8 + lq * 4 + 0][lm] = rb1.x; Bs[8 + lq * 4 + 1][lm] = rb1.y;
        Bs[8 + lq * 4 + 2][lm] = rb1.z; Bs[8 + lq * 4 + 3][lm] = rb1.w;
        __syncthreads();

        if (kt < 15) {
            int k0 = (kt + 1) * 16;
            const float* arow = emb + (size_t)tok[lm] * EMBD + k0;
            ra0 = *(const float4*)(arow + lq * 4);
            ra1 = *(const float4*)(arow + 8 + lq * 4);
            const float* brow = W + (size_t)(n0 + lm) * WROW + k0;
            rb0 = *(const float4*)(brow + lq * 4);
            rb1 = *(const float4*)(brow + 8 + lq * 4);
        }

#pragma unroll
        for (int k = 0; k < 16; k++) {
            float4 aL = *(const float4*)&As[k][ty * 4];
            float4 aH = *(const float4*)&As[k][64 + ty * 4];
            float4 bL = *(const float4*)&Bs[k][tx * 4];
            float4 bH = *(const float4*)&Bs[k][64 + tx * 4];
            float av[8] = {aL.x, aL.y, aL.z, aL.w, aH.x, aH.y, aH.z, aH.w};
            float bv[8] = {bL.x, bL.y, bL.z, bL.w, bH.x, bH.y, bH.z, bH.w};
#pragma unroll
            for (int i = 0; i < 8; i++)
#pragma unroll
                for (int jj = 0; jj < 8; jj++)
                    acc[i][jj] = fmaf(av[i], bv[jj], acc[i][jj]);
        }
        __syncthreads();
    }

    {
        float4 biL = *(const float4*)(bias + n0 + tx * 4);
        float4 biH = *(const float4*)(bias + n0 + 64 + tx * 4);
        float bl[8] = {biL.x, biL.y, biL.z, biL.w, biH.x, biH.y, biH.z, biH.w};
#pragma unroll
        for (int r = 0; r < 8; r++)
#pragma unroll
            for (int cc = 0; cc < 8; cc++) acc[r][cc] += bl[cc];
    }

    // transposed store: 8 stages of 16 columns through As (16x128 floats)
    float* T = &As[0][0];
    for (int s = 0; s < 8; s++) {
        __syncthreads();
        int txg = s & 3;
        int jbase = (s < 4) ? 0 : 4;
        if ((tx >> 2) == txg) {
#pragma unroll
            for (int q = 0; q < 4; q++) {
                int cl = (tx & 3) * 4 + q;
#pragma unroll
                for (int r = 0; r < 8; r++) {
                    int m_loc = (r >> 2) * 64 + ty * 4 + (r & 3);
                    T[cl * 128 + m_loc] = acc[r][jbase + q];
                }
            }
        }
        __syncthreads();
#pragma unroll
        for (int w = 0; w < 2; w++) {
            int v = tid + w * 256;
            int row = v >> 4;
            int within = v & 15;
            int cl = row >> 1, tl = row & 1;
            float4 val = *(float4*)&T[cl * 128 + tl * 64 + within * 4];
            int t = (m0 >> 6) + tl;
            int gcol = n0 + s * 16 + cl;
            *(float4*)&g_Gx[((size_t)t * NG + gcol) * BATCH + within * 4] = val;
        }
    }
}

// ============================================================================
// Kernel 2: persistent LSTM recurrence. 128 CTAs x 512 threads (16 warps,
//   4/SMSP). Warp = (jp in 0..1, ko in 0..7). Thread handles TWO j values
//   (j = 4bx + 2jp + {0,1}) and TWO batches (l, l+32) over a 16-f4 k-slice:
//   2 h loads + 8 weight broadcasts feed 32 fma2 -> crossbar = FMA floor.
//   8-way k reduction through smem (interleaved conflict-free layout).
// ============================================================================
__global__ __launch_bounds__(512, 1) void lstm_kernel(const float* __restrict__ W)
{
    extern __shared__ float smem[];
    float* hs = smem;                                  // 64 x 516
    float* ws = smem + BATCH * HS_STRIDE;              // 16 x 512
    unsigned long long* red =
        (unsigned long long*)(smem + BATCH * HS_STRIDE + 16 * HID); // 16 x 448

    const int tid  = threadIdx.x;
    const int bx   = blockIdx.x;
    const int l    = tid & 31;             // b0 = l, b1 = l + 32
    const int warp = tid >> 5;
    const int jp   = warp & 1;             // j-pair: j = 4bx + 2jp + jj
    const int ko   = warp >> 1;            // 0..7, k-slice of 16 f4
    const unsigned base = g_epoch;

    for (int i = tid; i < 16 * HID; i += 512) {
        int row = i >> 9;
        int k   = i & 511;
        int jlw = row >> 2, g = row & 3;
        ws[i] = W[(size_t)(g * HID + bx * 4 + jlw) * WROW + EMBD + k];
    }
    for (int i = bx * 512 + tid; i < BATCH * HID; i += NCTA * 512)
        g_h[0][i] = 0.f;

    gbar(bx, tid, base + 1);

    // weight pointers: [jj][g], broadcast within warp
    const float4* w00 = (const float4*)(ws + ((jp * 2 + 0) * 4 + 0) * HID) + ko * 16;
    const float4* w01 = (const float4*)(ws + ((jp * 2 + 0) * 4 + 1) * HID) + ko * 16;
    const float4* w02 = (const float4*)(ws + ((jp * 2 + 0) * 4 + 2) * HID) + ko * 16;
    const float4* w03 = (const float4*)(ws + ((jp * 2 + 0) * 4 + 3) * HID) + ko * 16;
    const float4* w10 = (const float4*)(ws + ((jp * 2 + 1) * 4 + 0) * HID) + ko * 16;
    const float4* w11 = (const float4*)(ws + ((jp * 2 + 1) * 4 + 1) * HID) + ko * 16;
    const float4* w12 = (const float4*)(ws + ((jp * 2 + 1) * 4 + 2) * HID) + ko * 16;
    const float4* w13 = (const float4*)(ws + ((jp * 2 + 1) * 4 + 3) * HID) + ko * 16;
    const float4* hp0 = (const float4*)(hs + l * HS_STRIDE) + ko * 16;
    const float4* hp1 = (const float4*)(hs + (l + 32) * HS_STRIDE) + ko * 16;

    // state: [jj][bsel], finalizer (ko==0) warps only
    float C00 = 0.f, C01 = 0.f, C10 = 0.f, C11 = 0.f;
    float h00 = 0.f, h01 = 0.f, h10 = 0.f, h11 = 0.f;
    int cur = 0;

    for (int t = 0; t < SEQ; t++) {
        // finalizer gate-bias loads (2j x 4g x 2b = 16)
        float gx[16];
        if (ko == 0) {
            const float* gxt = g_Gx + (size_t)t * NG * BATCH;
#pragma unroll
            for (int jj = 0; jj < 2; jj++)
#pragma unroll
                for (int g = 0; g < 4; g++) {
                    size_t rowoff = (size_t)(g * HID + bx * 4 + jp * 2 + jj) * BATCH;
                    gx[(jj * 4 + g) * 2 + 0] = __ldcg(gxt + rowoff + l);
                    gx[(jj * 4 + g) * 2 + 1] = __ldcg(gxt + rowoff + l + 32);
                }
        }

        // single-shot FULL restage: 8192 f4 over 512 threads; batched LDGs
        {
            const float4* src = (const float4*)g_h[cur];   // rows of 128 f4
            float4* dst = (float4*)hs;                     // rows of 129 f4
            float4 rr[16];
#pragma unroll
            for (int i = 0; i < 16; i++) {
                int e = tid + (i << 9);
                rr[i] = __ldcg(src + (e >> 7) * 128 + (e & 127));
            }
#pragma unroll
            for (int i = 0; i < 16; i++) {
                int e = tid + (i << 9);
                dst[(e >> 7) * 129 + (e & 127)] = rr[i];
            }
        }
        __syncthreads();

        unsigned long long a0[8], a1[8];   // [jj*4+g] for b0, b1
#pragma unroll
        for (int i = 0; i < 8; i++) { a0[i] = 0ull; a1[i] = 0ull; }

#pragma unroll
        for (int it = 0; it < 16; it++) {
            U4 ha, hb;
            ha.f = hp0[it]; hb.f = hp1[it];
            U4 w;
            w.f = w00[it];
            fma2(a0[0], ha.u.x, w.u.x); fma2(a0[0], ha.u.y, w.u.y);
            fma2(a1[0], hb.u.x, w.u.x); fma2(a1[0], hb.u.y, w.u.y);
            w.f = w01[it];
            fma2(a0[1], ha.u.x, w.u.x); fma2(a0[1], ha.u.y, w.u.y);
            fma2(a1[1], hb.u.x, w.u.x); fma2(a1[1], hb.u.y, w.u.y);
            w.f = w02[it];
            fma2(a0[2], ha.u.x, w.u.x); fma2(a0[2], ha.u.y, w.u.y);
            fma2(a1[2], hb.u.x, w.u.x); fma2(a1[2], hb.u.y, w.u.y);
            w.f = w03[it];
            fma2(a0[3], ha.u.x, w.u.x); fma2(a0[3], ha.u.y, w.u.y);
            fma2(a1[3], hb.u.x, w.u.x); fma2(a1[3], hb.u.y, w.u.y);
            w.f = w10[it];
            fma2(a0[4], ha.u.x, w.u.x); fma2(a0[4], ha.u.y, w.u.y);
            fma2(a1[4], hb.u.x, w.u.x); fma2(a1[4], hb.u.y, w.u.y);
            w.f = w11[it];
            fma2(a0[5], ha.u.x, w.u.x); fma2(a0[5], ha.u.y, w.u.y);
            fma2(a1[5], hb.u.x, w.u.x); fma2(a1[5], hb.u.y, w.u.y);
            w.f = w12[it];
            fma2(a0[6], ha.u.x, w.u.x); fma2(a0[6], ha.u.y, w.u.y);
            fma2(a1[6], hb.u.x, w.u.x); fma2(a1[6], hb.u.y, w.u.y);
            w.f = w13[it];
            fma2(a0[7], ha.u.x, w.u.x); fma2(a0[7], ha.u.y, w.u.y);
            fma2(a1[7], hb.u.x, w.u.x); fma2(a1[7], hb.u.y, w.u.y);
        }

        if (ko) {
            // interleaved layout: red[idx*448 + wid], wid = ((ko-1)*2+jp)*32+l
            unsigned long long* r = red + ((ko - 1) * 2 + jp) * 32 + l;
#pragma unroll
            for (int i = 0; i < 8; i++) {
                r[(2 * i) * 448]     = a0[i];
                r[(2 * i + 1) * 448] = a1[i];
            }
        }
        __syncthreads();
        if (ko == 0) {
            const unsigned long long* r = red + jp * 32 + l;
#pragma unroll
            for (int s = 0; s < 7; s++) {
                const unsigned long long* rs = r + s * 64;
#pragma unroll
                for (int i = 0; i < 8; i++) {
                    add2(a0[i], rs[(2 * i) * 448]);
                    add2(a1[i], rs[(2 * i + 1) * 448]);
                }
            }

            float* gh = g_h[cur ^ 1];
            const int j0 = bx * 4 + jp * 2;
            // jj = 0
            {
                float af = usum(a0[0]) + gx[0],  ai = usum(a0[1]) + gx[2];
                float ao = usum(a0[2]) + gx[4],  ac = usum(a0[3]) + gx[6];
                float F = fsig(af), I = fsig(ai), O = fsig(ao);
                C00 = F * C00 + I * ftanh(ac);
                h00 = O * ftanh(C00);

                af = usum(a1[0]) + gx[1];  ai = usum(a1[1]) + gx[3];
                ao = usum(a1[2]) + gx[5];  ac = usum(a1[3]) + gx[7];
                F = fsig(af); I = fsig(ai); O = fsig(ao);
                C01 = F * C01 + I * ftanh(ac);
                h01 = O * ftanh(C01);
                gh[l * HID + j0]        = h00;
                gh[(l + 32) * HID + j0] = h01;
            }
            // jj = 1
            {
                float af = usum(a0[4]) + gx[8],  ai = usum(a0[5]) + gx[10];
                float ao = usum(a0[6]) + gx[12], ac = usum(a0[7]) + gx[14];
                float F = fsig(af), I = fsig(ai), O = fsig(ao);
                C10 = F * C10 + I * ftanh(ac);
                h10 = O * ftanh(C10);

                af = usum(a1[4]) + gx[9];  ai = usum(a1[5]) + gx[11];
                ao = usum(a1[6]) + gx[13]; ac = usum(a1[7]) + gx[15];
                F = fsig(af); I = fsig(ai); O = fsig(ao);
                C11 = F * C11 + I * ftanh(ac);
                h11 = O * ftanh(C11);
                gh[l * HID + j0 + 1]        = h10;
                gh[(l + 32) * HID + j0 + 1] = h11;
            }
        }

        gbar(bx, tid, base + 2 + t);
        cur ^= 1;
    }

    if (ko == 0) {
        const int j0 = bx * 4 + jp * 2;
        g_hbt[(size_t)j0 * BATCH + l]            = h00;
        g_hbt[(size_t)j0 * BATCH + l + 32]       = h01;
        g_hbt[(size_t)(j0 + 1) * BATCH + l]      = h10;
        g_hbt[(size_t)(j0 + 1) * BATCH + l + 32] = h11;
    }
    if (bx == 0 && tid == 0) g_epoch = base + SEQ + 8;
}

// ============================================================================
// Kernel 3: out[b][n] = h[b] . fc_weight[n] + fc_bias[n]
//   h staged in smem as [k][b] padded rows; f32x2 over batch pairs.
// ============================================================================
__global__ __launch_bounds__(256, 1) void fc_kernel(
    const float* __restrict__ fcw, const float* __restrict__ fcb,
    float* __restrict__ out)
{
    extern __shared__ float hb2[];   // 512 rows x 68 floats
    const int tid = threadIdx.x;
    for (int i = tid; i < HID * 16; i += 256) {
        int k = i >> 4, q = i & 15;
        ((float4*)(hb2 + k * 68))[q] = ((const float4*)g_hbt)[i];
    }
    __syncthreads();

    const int warp = tid >> 5, lane = tid & 31;
    const int wglobal = blockIdx.x * 8 + warp;
    const int nw = gridDim.x * 8;

    for (int n = wglobal; n < NCLS; n += nw) {
        unsigned long long acc[32];
#pragma unroll
        for (int i = 0; i < 32; i++) acc[i] = 0ull;
        const float* wrow = fcw + (size_t)n * HID;
#pragma unroll
        for (int kk = 0; kk < 16; kk++) {
            int k = kk * 32 + lane;
            unsigned long long ww = pack2(wrow[k]);
            const float4* hrow = (const float4*)(hb2 + k * 68);
#pragma unroll
            for (int q = 0; q < 16; q++) {
                U4 hh; hh.f = hrow[q];
                fma2(acc[2 * q],     ww, hh.u.x);
                fma2(acc[2 * q + 1], ww, hh.u.y);
            }
        }
        float bias = fcb[n];
#pragma unroll
        for (int p = 0; p < 32; p++) {
            unsigned long long v = acc[p];
            add2(v, __shfl_xor_sync(0xffffffffu, v, 16));
            add2(v, __shfl_xor_sync(0xffffffffu, v, 8));
            add2(v, __shfl_xor_sync(0xffffffffu, v, 4));
            add2(v, __shfl_xor_sync(0xffffffffu, v, 2));
            add2(v, __shfl_xor_sync(0xffffffffu, v, 1));
            if (lane == 0) {
                U2 u; u.u = v;
                out[(size_t)(2 * p) * NCLS + n]     = u.f.x + bias;
                out[(size_t)(2 * p + 1) * NCLS + n] = u.f.y + bias;
            }
        }
    }
}

// ============================================================================
extern "C" void kernel_launch(void* const* d_in, const int* in_sizes, int n_in,
                              void* d_out, int out_size)
{
    const int*   x   = (const int*)d_in[0];
    const float* emb = (const float*)d_in[1];
    const float* W   = (const float*)d_in[2];
    const float* Wb  = (const float*)d_in[3];
    const float* fcw = (const float*)d_in[4];
    const float* fcb = (const float*)d_in[5];
    float* out = (float*)d_out;

    // hs 132096 B + ws 32768 B + red 16*448*8 = 57344 B -> 222208 B
    static const size_t lstm_smem =
        (size_t)(BATCH * HS_STRIDE + 16 * HID) * 4 + (size_t)16 * 448 * 8;
    static const size_t fc_smem = (size_t)HID * 68 * 4;      // 139264
    cudaFuncSetAttribute(lstm_kernel, cudaFuncAttributeMaxDynamicSharedMemorySize,
                         (int)lstm_smem);
    cudaFuncSetAttribute(fc_kernel, cudaFuncAttributeMaxDynamicSharedMemorySize,
                         (int)fc_smem);

    dim3 g1(SEQ * BATCH / 128, NG / 128);
    gx_kernel<<<g1, 256>>>(x, emb, W, Wb);

    lstm_kernel<<<NCTA, 512, lstm_smem>>>(W);

    fc_kernel<<<148, 256, fc_smem>>>(fcw, fcb, out);
}